// round 8
// baseline (speedup 1.0000x reference)
#include <cuda_runtime.h>
#include <cuda_bf16.h>
#include <math.h>
#include <stdint.h>

// ---------------- problem dims ----------------
#define B_   512
#define T_   256
#define H_   1024
#define C_   128

// ---------------- step-kernel tiling ----------------
#define BM 64
#define BN 64
#define BK 64
#define KP 72                      // padded k-stride (elems) -> conflict-free ldmatrix
#define NCH (H_ / BK)              // 16 chunks
#define ARR_BYTES (64 * KP * 2)    // 9216 per operand array
#define STG_BYTES (4 * ARR_BYTES)  // 36864 per stage
#define NSTAGE 4
#define STEP_SMEM (NSTAGE * STG_BYTES)   // 147456 bytes

// ---------------- device scratch (no runtime allocation allowed) ----------------
__device__ float          g_h[B_ * H_];
__device__ __nv_bfloat16  g_whi[H_ * H_], g_wlo[H_ * H_];
__device__ __nv_bfloat16  g_ahi[2][B_ * H_], g_alo[2][B_ * H_];
__device__ float          g_parto[4][B_ * C_];

// ---------------- base-ISA PTX helpers (compute_103-safe) ----------------
__device__ __forceinline__ uint32_t smem_u32(const void* p) {
    uint32_t a;
    asm("{ .reg .u64 t; cvta.to.shared.u64 t, %1; cvt.u32.u64 %0, t; }"
        : "=r"(a) : "l"(p));
    return a;
}
#define CP16(d, s) \
    asm volatile("cp.async.cg.shared.global [%0], [%1], 16;" :: "r"(d), "l"(s))
#define CPCOMMIT() asm volatile("cp.async.commit_group;" ::: "memory")
#define CPWAIT(n)  asm volatile("cp.async.wait_group %0;" :: "n"(n) : "memory")

#define LDSM4(r, addr) \
    asm volatile("ldmatrix.sync.aligned.m8n8.x4.shared.b16 {%0,%1,%2,%3}, [%4];" \
        : "=r"((r)[0]), "=r"((r)[1]), "=r"((r)[2]), "=r"((r)[3]) : "r"(addr))

#define MMA16816(c, a, b0, b1) \
    asm volatile("mma.sync.aligned.m16n8k16.row.col.f32.bf16.bf16.f32 " \
        "{%0,%1,%2,%3}, {%4,%5,%6,%7}, {%8,%9}, {%0,%1,%2,%3};" \
        : "+f"((c)[0]), "+f"((c)[1]), "+f"((c)[2]), "+f"((c)[3]) \
        : "r"((a)[0]), "r"((a)[1]), "r"((a)[2]), "r"((a)[3]), "r"(b0), "r"(b1))

// =====================================================================
// per-step kernel: acc = Ahi*Whi^T + Ahi*Wlo^T + Alo*Whi^T (all bf16 MMA),
// fused epilogue h = tanh(acc + x_t*W_hx + b_h), writes next hi/lo splits.
// grid (16, 8) = 128 CTAs, 512 threads (16 warps, warp tile 16x16 -> 4/SMSP).
// 4-stage cp.async pipeline, ONE __syncthreads per 64-k chunk.
// =====================================================================
__global__ void __launch_bounds__(512, 1)
rnn_step(const __nv_bfloat16* __restrict__ ahi, const __nv_bfloat16* __restrict__ alo,
         const __nv_bfloat16* __restrict__ whi, const __nv_bfloat16* __restrict__ wlo,
         const float* __restrict__ x, const float* __restrict__ whx,
         const float* __restrict__ bh,
         float* __restrict__ hout,
         __nv_bfloat16* __restrict__ ahi_o, __nv_bfloat16* __restrict__ alo_o,
         int t, int last)
{
    extern __shared__ char smem[];
    const uint32_t sb = smem_u32(smem);
    const int tid  = threadIdx.x;
    const int wid  = tid >> 5;
    const int lane = tid & 31;
    const int bn   = blockIdx.x;
    const int bm   = blockIdx.y;
    const int wm   = (wid & 3) * 16;    // warp tile m origin (4 m-warps)
    const int wn   = (wid >> 2) * 16;   // warp tile n origin (4 n-warps)

    const __nv_bfloat16* srcs[4] = {
        ahi + (size_t)(bm * BM) * H_,
        alo + (size_t)(bm * BM) * H_,
        whi + (size_t)(bn * BN) * H_,
        wlo + (size_t)(bn * BN) * H_
    };

    float acc[2][4];                    // [ni][quad]
#pragma unroll
    for (int ni = 0; ni < 2; ni++)
#pragma unroll
        for (int q = 0; q < 4; q++) acc[ni][q] = 0.0f;

    // global-load mapping: 1 cp.async per thread per operand array
    const int grow = tid >> 3;          // 0..63
    const int gko  = (tid & 7) * 8;     // 0..56

    auto LOAD = [&](int ch, int slot) {
        const uint32_t base = sb + slot * STG_BYTES
                            + (uint32_t)(grow * KP + gko) * 2;
        const size_t goff = (size_t)grow * H_ + ch * BK + gko;
#pragma unroll
        for (int r = 0; r < 4; r++)
            CP16(base + r * ARR_BYTES, srcs[r] + goff);
    };

    const int tdiv8 = lane >> 3;
    const int tmod8 = lane & 7;
    // ldmatrix source rows (fixed per thread; col varies with ks)
    const int arow = wm + ((tdiv8 & 1) << 3) + tmod8;   // A: tiles m0-7/m8-15 x k0-7/k8-15
    const int wrow = wn + ((tdiv8 >> 1) << 3) + tmod8;  // W: tiles n0-7/n8-15 x k0-7/k8-15

    auto COMPUTE = [&](int slot) {
        const uint32_t base = sb + slot * STG_BYTES;
#pragma unroll
        for (int ks = 0; ks < 4; ks++) {
            uint32_t Ah[4], Al[4], Wh[4], Wl[4];
            {
                const int col = ks * 16 + ((tdiv8 >> 1) << 3);
                const uint32_t off = base + (uint32_t)(arow * KP + col) * 2;
                LDSM4(Ah, off);                    // aHI
                LDSM4(Al, off + ARR_BYTES);        // aLO
            }
            {
                const int col = ks * 16 + ((tdiv8 & 1) << 3);
                const uint32_t off = base + (uint32_t)(wrow * KP + col) * 2;
                LDSM4(Wh, off + 2 * ARR_BYTES);    // wHI
                LDSM4(Wl, off + 3 * ARR_BYTES);    // wLO
            }
            // products: Ahi*Whi, Ahi*Wlo, Alo*Whi
#pragma unroll
            for (int p = 0; p < 3; p++) {
                uint32_t* A = (p == 2) ? Al : Ah;
                uint32_t* W = (p == 1) ? Wl : Wh;
#pragma unroll
                for (int ni = 0; ni < 2; ni++)
                    MMA16816(acc[ni], A, W[ni * 2], W[ni * 2 + 1]);
            }
        }
    };

    // ---------------- 4-stage cp.async mainloop, one barrier/chunk ----------------
    LOAD(0, 0); CPCOMMIT();
    LOAD(1, 1); CPCOMMIT();
    LOAD(2, 2); CPCOMMIT();
#pragma unroll 1
    for (int c = 0; c < NCH; c++) {
        if (c < NCH - 2)       { CPWAIT(2); }   // group c complete
        else if (c == NCH - 2) { CPWAIT(1); }
        else                   { CPWAIT(0); }
        __syncthreads();                         // all warps done with slot (c+3)&3's old data
        if (c + 3 < NCH) { LOAD(c + 3, (c + 3) & 3); CPCOMMIT(); }
        COMPUTE(c & 3);
    }

    // ---------------- fused epilogue ----------------
    const int qc = (lane & 3) * 2;
#pragma unroll
    for (int ni = 0; ni < 2; ni++) {
        const int j = bn * BN + wn + ni * 8 + qc;
        const float w0 = whx[j],     w1 = whx[j + 1];
        const float b0 = bh[j],      b1 = bh[j + 1];
#pragma unroll
        for (int hf = 0; hf < 2; hf++) {
            const int row = wm + (lane >> 2) + hf * 8;
            const int gm  = bm * BM + row;
            const float xv = x[(size_t)gm * T_ + t];
            const float c0 = acc[ni][hf * 2];
            const float c1 = acc[ni][hf * 2 + 1];
            const float h0 = tanhf(fmaf(xv, w0, b0) + c0);
            const float h1 = tanhf(fmaf(xv, w1, b1) + c1);
            const size_t o = (size_t)gm * H_ + j;
            const __nv_bfloat16 h0h = __float2bfloat16(h0);
            const __nv_bfloat16 h1h = __float2bfloat16(h1);
            __nv_bfloat162 hi2; hi2.x = h0h; hi2.y = h1h;
            *reinterpret_cast<__nv_bfloat162*>(ahi_o + o) = hi2;
            __nv_bfloat162 lo2;
            lo2.x = __float2bfloat16(h0 - __bfloat162float(h0h));
            lo2.y = __float2bfloat16(h1 - __bfloat162float(h1h));
            *reinterpret_cast<__nv_bfloat162*>(alo_o + o) = lo2;
            if (last) {
                float2 f2; f2.x = h0; f2.y = h1;
                *reinterpret_cast<float2*>(hout + o) = f2;
            }
        }
    }
}

// ================= one-time helpers =================
__global__ void split_w(const float* __restrict__ w,
                        __nv_bfloat16* __restrict__ hi, __nv_bfloat16* __restrict__ lo)
{
    const int i = (blockIdx.x * blockDim.x + threadIdx.x) * 4;
    float4 v = *reinterpret_cast<const float4*>(w + i);
    const float vv[4] = { v.x, v.y, v.z, v.w };
#pragma unroll
    for (int q = 0; q < 4; q++) {
        __nv_bfloat16 h = __float2bfloat16(vv[q]);
        hi[i + q] = h;
        lo[i + q] = __float2bfloat16(vv[q] - __bfloat162float(h));
    }
}

__global__ void init_h(const float* __restrict__ x, const float* __restrict__ whx,
                       const float* __restrict__ bh,
                       __nv_bfloat16* __restrict__ ahi, __nv_bfloat16* __restrict__ alo)
{
    const int idx = blockIdx.x * blockDim.x + threadIdx.x;  // 131072
    const int b = idx >> 8;
    const int j0 = (idx & 255) << 2;
    const float xv = x[(size_t)b * T_];      // t = 0
#pragma unroll
    for (int q = 0; q < 4; q++) {
        const int j = j0 + q;
        const float hs = tanhf(fmaf(xv, whx[j], bh[j]));
        const size_t o = (size_t)b * H_ + j;
        __nv_bfloat16 hb = __float2bfloat16(hs);
        ahi[o] = hb;
        alo[o] = __float2bfloat16(hs - __bfloat162float(hb));
    }
}

// ================= head GEMM (proven SIMT split-K, N=128) =================
#define GBM   128
#define GBK   32
#define GBMp  132
#define GKS   4
#define GKPS  (H_ / GKS)
#define GNCH  (GKPS / GBK)

__device__ __forceinline__ void ffma2(unsigned long long& d,
                                      unsigned long long a, unsigned long long b) {
    asm("fma.rn.f32x2 %0, %1, %2, %0;" : "+l"(d) : "l"(a), "l"(b));
}
__device__ __forceinline__ unsigned long long dup2(float w) {
    unsigned long long r;
    asm("mov.b64 %0, {%1, %1};" : "=l"(r) : "f"(w));
    return r;
}

__global__ void __launch_bounds__(256, 1)
gemm_part_kernel(const float* __restrict__ A, const float* __restrict__ W,
                 float* __restrict__ part, int N)
{
    extern __shared__ float fsm[];
    float (*Hs)[GBK][GBMp] = reinterpret_cast<float (*)[GBK][GBMp]>(fsm);
    float (*Ws)[GBK][GBMp] = reinterpret_cast<float (*)[GBK][GBMp]>(fsm + 2 * GBK * GBMp);

    const int tid = threadIdx.x;
    const int bn = blockIdx.x, bm = blockIdx.y, ks = blockIdx.z;
    const int k0 = ks * GKPS;
    const int lr = tid >> 3, lk = (tid & 7) << 2;
    const float* Ag = A + (size_t)(bm * GBM + lr) * H_ + k0 + lk;
    const float* Wg = W + (size_t)(bn * 128 + lr) * H_ + k0 + lk;
    const int tm = (tid & 15) * 8, tn = (tid >> 4) * 8;

    unsigned long long acc[4][8];
#pragma unroll
    for (int i = 0; i < 4; i++)
#pragma unroll
        for (int j = 0; j < 8; j++) acc[i][j] = 0ull;

    float4 ra[4], rb[4];
    auto LDG = [&](int ch) {
        const float* a = Ag + ch * GBK;
        const float* w = Wg + ch * GBK;
#pragma unroll
        for (int p = 0; p < 4; p++) {
            ra[p] = *reinterpret_cast<const float4*>(a + (size_t)p * 32 * H_);
            rb[p] = *reinterpret_cast<const float4*>(w + (size_t)p * 32 * H_);
        }
    };
    auto STS = [&](int buf) {
#pragma unroll
        for (int p = 0; p < 4; p++) {
            const float* va = reinterpret_cast<const float*>(&ra[p]);
            const float* vb = reinterpret_cast<const float*>(&rb[p]);
            const int m = p * 32 + lr;
#pragma unroll
            for (int q = 0; q < 4; q++) {
                Hs[buf][lk + q][m] = va[q];
                Ws[buf][lk + q][m] = vb[q];
            }
        }
    };
    auto COMPUTE = [&](int buf) {
#pragma unroll 4
        for (int kk = 0; kk < GBK; kk++) {
            ulonglong2 hA = *reinterpret_cast<const ulonglong2*>(&Hs[buf][kk][tm]);
            ulonglong2 hB = *reinterpret_cast<const ulonglong2*>(&Hs[buf][kk][tm + 4]);
            float4 wa = *reinterpret_cast<const float4*>(&Ws[buf][kk][tn]);
            float4 wb = *reinterpret_cast<const float4*>(&Ws[buf][kk][tn + 4]);
            unsigned long long h[4] = { hA.x, hA.y, hB.x, hB.y };
            unsigned long long w[8] = { dup2(wa.x), dup2(wa.y), dup2(wa.z), dup2(wa.w),
                                        dup2(wb.x), dup2(wb.y), dup2(wb.z), dup2(wb.w) };
#pragma unroll
            for (int i = 0; i < 4; i++)
#pragma unroll
                for (int j = 0; j < 8; j++) ffma2(acc[i][j], h[i], w[j]);
        }
    };

    LDG(0); STS(0); LDG(1);
    __syncthreads();
#pragma unroll 1
    for (int ch = 0; ch < GNCH; ch++) {
        const int buf = ch & 1;
        if (ch + 1 < GNCH) STS(buf ^ 1);
        if (ch + 2 < GNCH) LDG(ch + 2);
        COMPUTE(buf);
        __syncthreads();
    }

    float* P = part + (size_t)ks * B_ * N + (size_t)(bm * GBM) * N + bn * 128;
#pragma unroll
    for (int i = 0; i < 4; i++) {
        const int r0 = tm + 2 * i;
        float2 f[8];
#pragma unroll
        for (int j = 0; j < 8; j++) f[j] = *reinterpret_cast<float2*>(&acc[i][j]);
        *reinterpret_cast<float4*>(P + (size_t)r0 * N + tn)           = make_float4(f[0].x, f[1].x, f[2].x, f[3].x);
        *reinterpret_cast<float4*>(P + (size_t)r0 * N + tn + 4)       = make_float4(f[4].x, f[5].x, f[6].x, f[7].x);
        *reinterpret_cast<float4*>(P + (size_t)(r0 + 1) * N + tn)     = make_float4(f[0].y, f[1].y, f[2].y, f[3].y);
        *reinterpret_cast<float4*>(P + (size_t)(r0 + 1) * N + tn + 4) = make_float4(f[4].y, f[5].y, f[6].y, f[7].y);
    }
}

__global__ void combine_o(const float* __restrict__ parto,
                          const float* __restrict__ bp, float* __restrict__ out)
{
    const int idx = blockIdx.x * blockDim.x + threadIdx.x;
    const int b = idx >> 5;
    const int c = (idx & 31) << 2;
    float4 s = *reinterpret_cast<const float4*>(bp + c);
    const size_t off = (size_t)b * C_ + c;
#pragma unroll
    for (int z = 0; z < GKS; z++) {
        float4 p = *reinterpret_cast<const float4*>(parto + (size_t)z * B_ * C_ + off);
        s.x += p.x; s.y += p.y; s.z += p.z; s.w += p.w;
    }
    *reinterpret_cast<float4*>(out + off) = s;
}

// ================= launch =================
extern "C" void kernel_launch(void* const* d_in, const int* in_sizes, int n_in,
                              void* d_out, int out_size)
{
    const float* x   = (const float*)d_in[0];   // [512,256]
    const float* whx = (const float*)d_in[1];   // [1024,1]
    const float* whh = (const float*)d_in[2];   // [1024,1024]
    const float* bh  = (const float*)d_in[3];   // [1024]
    const float* wph = (const float*)d_in[4];   // [128,1024]
    const float* bp  = (const float*)d_in[5];   // [128]
    float* out = (float*)d_out;                 // [512,128]

    float *h, *parto;
    __nv_bfloat16 *wh_hi, *wh_lo, *a_hi, *a_lo;
    cudaGetSymbolAddress((void**)&h,     g_h);
    cudaGetSymbolAddress((void**)&wh_hi, g_whi);
    cudaGetSymbolAddress((void**)&wh_lo, g_wlo);
    cudaGetSymbolAddress((void**)&a_hi,  g_ahi);
    cudaGetSymbolAddress((void**)&a_lo,  g_alo);
    cudaGetSymbolAddress((void**)&parto, g_parto);

    cudaFuncSetAttribute(rnn_step, cudaFuncAttributeMaxDynamicSharedMemorySize, STEP_SMEM);
    const size_t gsmem = (size_t)2 * GBK * GBMp * sizeof(float) * 2;
    cudaFuncSetAttribute(gemm_part_kernel, cudaFuncAttributeMaxDynamicSharedMemorySize, (int)gsmem);

    // one-time: split W_hh into hi/lo bf16
    split_w<<<1024, 256>>>(whh, wh_hi, wh_lo);

    // step 0: h = tanh(x_0 * W_hx^T + b_h)
    init_h<<<512, 256>>>(x, whx, bh, a_hi, a_lo);

    // steps 1..255 on tensor cores (base-ISA mma.sync path)
    const size_t HB = (size_t)B_ * H_;
    for (int t = 1; t < T_; t++) {
        const int ib = (t - 1) & 1, ob = t & 1;
        rnn_step<<<dim3(H_ / BN, B_ / BM), 512, STEP_SMEM>>>(
            a_hi + (size_t)ib * HB, a_lo + (size_t)ib * HB,
            wh_hi, wh_lo, x, whx, bh,
            h, a_hi + (size_t)ob * HB, a_lo + (size_t)ob * HB,
            t, (t == T_ - 1) ? 1 : 0);
    }

    // head: out = h_last @ W_ph^T + b_p
    gemm_part_kernel<<<dim3(1, B_ / GBM, GKS), 256, gsmem>>>(h, wph, parto, C_);
    combine_o<<<(B_ * C_ / 4) / 256, 256>>>(parto, bp, out);
}

// round 9
// speedup vs baseline: 1.1347x; 1.1347x over previous
#include <cuda_runtime.h>
#include <cuda_bf16.h>
#include <math.h>
#include <stdint.h>

// ---------------- problem dims ----------------
#define B_   512
#define T_   256
#define H_   1024
#define C_   128

// ---------------- step-kernel tiling ----------------
#define BM 64
#define BN 64
#define BK 128
#define KP 136                     // padded k-stride (elems) -> conflict-free ldmatrix
#define NCH (H_ / BK)              // 8 chunks
#define ARR_BYTES (64 * KP * 2)    // 17408 per operand array
#define STG_BYTES (4 * ARR_BYTES)  // 69632 per stage
#define NSTAGE 3
#define STEP_SMEM (NSTAGE * STG_BYTES)   // 208896 bytes

// ---------------- device scratch (no runtime allocation allowed) ----------------
__device__ float          g_h[B_ * H_];
__device__ __nv_bfloat16  g_whi[H_ * H_], g_wlo[H_ * H_];
__device__ __nv_bfloat16  g_ahi[2][B_ * H_], g_alo[2][B_ * H_];
__device__ float          g_parto[4][B_ * C_];

// ---------------- base-ISA PTX helpers (compute_103-safe) ----------------
__device__ __forceinline__ uint32_t smem_u32(const void* p) {
    uint32_t a;
    asm("{ .reg .u64 t; cvta.to.shared.u64 t, %1; cvt.u32.u64 %0, t; }"
        : "=r"(a) : "l"(p));
    return a;
}
#define CP16(d, s) \
    asm volatile("cp.async.cg.shared.global [%0], [%1], 16;" :: "r"(d), "l"(s))
#define CPCOMMIT() asm volatile("cp.async.commit_group;" ::: "memory")
#define CPWAIT(n)  asm volatile("cp.async.wait_group %0;" :: "n"(n) : "memory")

#define LDSM4(r, addr) \
    asm volatile("ldmatrix.sync.aligned.m8n8.x4.shared.b16 {%0,%1,%2,%3}, [%4];" \
        : "=r"((r)[0]), "=r"((r)[1]), "=r"((r)[2]), "=r"((r)[3]) : "r"(addr))

#define MMA16816(c, a, b0, b1) \
    asm volatile("mma.sync.aligned.m16n8k16.row.col.f32.bf16.bf16.f32 " \
        "{%0,%1,%2,%3}, {%4,%5,%6,%7}, {%8,%9}, {%0,%1,%2,%3};" \
        : "+f"((c)[0]), "+f"((c)[1]), "+f"((c)[2]), "+f"((c)[3]) \
        : "r"((a)[0]), "r"((a)[1]), "r"((a)[2]), "r"((a)[3]), "r"(b0), "r"(b1))

// =====================================================================
// per-step kernel: acc = Ahi*Whi^T + Ahi*Wlo^T + Alo*Whi^T (all bf16 MMA),
// fused epilogue h = tanh(acc + x_t*W_hx + b_h), writes next hi/lo splits.
// grid (16, 8) = 128 CTAs, 256 threads (8 warps, warp tile 32x16).
// 3-stage cp.async pipeline, BK=128: only 8 barrier/wait rounds per step.
// =====================================================================
__global__ void __launch_bounds__(256, 1)
rnn_step(const __nv_bfloat16* __restrict__ ahi, const __nv_bfloat16* __restrict__ alo,
         const __nv_bfloat16* __restrict__ whi, const __nv_bfloat16* __restrict__ wlo,
         const float* __restrict__ x, const float* __restrict__ whx,
         const float* __restrict__ bh,
         float* __restrict__ hout,
         __nv_bfloat16* __restrict__ ahi_o, __nv_bfloat16* __restrict__ alo_o,
         int t, int last)
{
    extern __shared__ char smem[];
    const uint32_t sb = smem_u32(smem);
    const int tid  = threadIdx.x;
    const int wid  = tid >> 5;
    const int lane = tid & 31;
    const int bn   = blockIdx.x;
    const int bm   = blockIdx.y;
    const int wm   = (wid & 1) * 32;    // warp tile m origin (2 m-warps)
    const int wn   = (wid >> 1) * 16;   // warp tile n origin (4 n-warps)

    const __nv_bfloat16* srcs[4] = {
        ahi + (size_t)(bm * BM) * H_,
        alo + (size_t)(bm * BM) * H_,
        whi + (size_t)(bn * BN) * H_,
        wlo + (size_t)(bn * BN) * H_
    };

    // -------- prefetch epilogue constants before the mainloop --------
    const int qc = (lane & 3) * 2;
    float ew0[2], ew1[2], eb0[2], eb1[2];
#pragma unroll
    for (int ni = 0; ni < 2; ni++) {
        const int j = bn * BN + wn + ni * 8 + qc;
        ew0[ni] = whx[j];  ew1[ni] = whx[j + 1];
        eb0[ni] = bh[j];   eb1[ni] = bh[j + 1];
    }
    float exv[2][2];
#pragma unroll
    for (int mi = 0; mi < 2; mi++)
#pragma unroll
        for (int hf = 0; hf < 2; hf++) {
            const int gm = bm * BM + wm + mi * 16 + (lane >> 2) + hf * 8;
            exv[mi][hf] = x[(size_t)gm * T_ + t];
        }

    float acc[2][2][4];                 // [mi][ni][quad]
#pragma unroll
    for (int mi = 0; mi < 2; mi++)
#pragma unroll
        for (int ni = 0; ni < 2; ni++)
#pragma unroll
            for (int q = 0; q < 4; q++) acc[mi][ni][q] = 0.0f;

    // global-load mapping: 16 cp.async per thread per chunk (4 per array)
    auto LOAD = [&](int ch, int slot) {
        const uint32_t base = sb + slot * STG_BYTES;
        const int k0 = ch * BK;
#pragma unroll
        for (int r = 0; r < 4; r++) {
            const __nv_bfloat16* s = srcs[r];
            const uint32_t ab = base + r * ARR_BYTES;
#pragma unroll
            for (int i = 0; i < 4; i++) {
                const int u   = tid + i * 256;      // 0..1023
                const int row = u >> 4;             // 0..63
                const int ko  = (u & 15) * 8;       // 0..120
                CP16(ab + (uint32_t)(row * KP + ko) * 2,
                     s + (size_t)row * H_ + k0 + ko);
            }
        }
    };

    const int tdiv8 = lane >> 3;
    const int tmod8 = lane & 7;
    const int arow = wm + ((tdiv8 & 1) << 3) + tmod8;   // A ldmatrix row
    const int wrow = wn + ((tdiv8 >> 1) << 3) + tmod8;  // W ldmatrix row

    auto COMPUTE = [&](int slot) {
        const uint32_t base = sb + slot * STG_BYTES;
#pragma unroll
        for (int ks = 0; ks < 8; ks++) {
            uint32_t Ah[2][4], Al[2][4], Wh[4], Wl[4];
#pragma unroll
            for (int mi = 0; mi < 2; mi++) {
                const int row = arow + mi * 16;
                const int col = ks * 16 + ((tdiv8 >> 1) << 3);
                const uint32_t off = base + (uint32_t)(row * KP + col) * 2;
                LDSM4(Ah[mi], off);                    // aHI
                LDSM4(Al[mi], off + ARR_BYTES);        // aLO
            }
            {
                const int col = ks * 16 + ((tdiv8 & 1) << 3);
                const uint32_t off = base + (uint32_t)(wrow * KP + col) * 2;
                LDSM4(Wh, off + 2 * ARR_BYTES);        // wHI
                LDSM4(Wl, off + 3 * ARR_BYTES);        // wLO
            }
            // products: Ahi*Whi, Ahi*Wlo, Alo*Whi
#pragma unroll
            for (int p = 0; p < 3; p++) {
                uint32_t (*A)[4] = (p == 2) ? Al : Ah;
                uint32_t* W      = (p == 1) ? Wl : Wh;
#pragma unroll
                for (int mi = 0; mi < 2; mi++)
#pragma unroll
                    for (int ni = 0; ni < 2; ni++)
                        MMA16816(acc[mi][ni], A[mi], W[ni * 2], W[ni * 2 + 1]);
            }
        }
    };

    // ---------------- 3-stage cp.async mainloop, one barrier/chunk ----------------
    LOAD(0, 0); CPCOMMIT();
    LOAD(1, 1); CPCOMMIT();
#pragma unroll 1
    for (int c = 0; c < NCH; c++) {
        if (c < NCH - 1) { CPWAIT(1); }   // chunk c's group complete
        else             { CPWAIT(0); }
        __syncthreads();                   // slot (c+2)%3's old data fully consumed
        if (c + 2 < NCH) { LOAD(c + 2, (c + 2) % NSTAGE); CPCOMMIT(); }
        COMPUTE(c % NSTAGE);
    }

    // ---------------- fused epilogue (constants already in regs) ----------------
#pragma unroll
    for (int ni = 0; ni < 2; ni++) {
        const int j = bn * BN + wn + ni * 8 + qc;
#pragma unroll
        for (int mi = 0; mi < 2; mi++) {
#pragma unroll
            for (int hf = 0; hf < 2; hf++) {
                const int row = wm + mi * 16 + (lane >> 2) + hf * 8;
                const int gm  = bm * BM + row;
                const float xv = exv[mi][hf];
                const float c0 = acc[mi][ni][hf * 2];
                const float c1 = acc[mi][ni][hf * 2 + 1];
                const float h0 = tanhf(fmaf(xv, ew0[ni], eb0[ni]) + c0);
                const float h1 = tanhf(fmaf(xv, ew1[ni], eb1[ni]) + c1);
                const size_t o = (size_t)gm * H_ + j;
                const __nv_bfloat16 h0h = __float2bfloat16(h0);
                const __nv_bfloat16 h1h = __float2bfloat16(h1);
                __nv_bfloat162 hi2; hi2.x = h0h; hi2.y = h1h;
                *reinterpret_cast<__nv_bfloat162*>(ahi_o + o) = hi2;
                __nv_bfloat162 lo2;
                lo2.x = __float2bfloat16(h0 - __bfloat162float(h0h));
                lo2.y = __float2bfloat16(h1 - __bfloat162float(h1h));
                *reinterpret_cast<__nv_bfloat162*>(alo_o + o) = lo2;
                if (last) {
                    float2 f2; f2.x = h0; f2.y = h1;
                    *reinterpret_cast<float2*>(hout + o) = f2;
                }
            }
        }
    }
}

// ================= one-time helpers =================
__global__ void split_w(const float* __restrict__ w,
                        __nv_bfloat16* __restrict__ hi, __nv_bfloat16* __restrict__ lo)
{
    const int i = (blockIdx.x * blockDim.x + threadIdx.x) * 4;
    float4 v = *reinterpret_cast<const float4*>(w + i);
    const float vv[4] = { v.x, v.y, v.z, v.w };
#pragma unroll
    for (int q = 0; q < 4; q++) {
        __nv_bfloat16 h = __float2bfloat16(vv[q]);
        hi[i + q] = h;
        lo[i + q] = __float2bfloat16(vv[q] - __bfloat162float(h));
    }
}

__global__ void init_h(const float* __restrict__ x, const float* __restrict__ whx,
                       const float* __restrict__ bh,
                       __nv_bfloat16* __restrict__ ahi, __nv_bfloat16* __restrict__ alo)
{
    const int idx = blockIdx.x * blockDim.x + threadIdx.x;  // 131072
    const int b = idx >> 8;
    const int j0 = (idx & 255) << 2;
    const float xv = x[(size_t)b * T_];      // t = 0
#pragma unroll
    for (int q = 0; q < 4; q++) {
        const int j = j0 + q;
        const float hs = tanhf(fmaf(xv, whx[j], bh[j]));
        const size_t o = (size_t)b * H_ + j;
        __nv_bfloat16 hb = __float2bfloat16(hs);
        ahi[o] = hb;
        alo[o] = __float2bfloat16(hs - __bfloat162float(hb));
    }
}

// ================= head GEMM (proven SIMT split-K, N=128) =================
#define GBM   128
#define GBK   32
#define GBMp  132
#define GKS   4
#define GKPS  (H_ / GKS)
#define GNCH  (GKPS / GBK)

__device__ __forceinline__ void ffma2(unsigned long long& d,
                                      unsigned long long a, unsigned long long b) {
    asm("fma.rn.f32x2 %0, %1, %2, %0;" : "+l"(d) : "l"(a), "l"(b));
}
__device__ __forceinline__ unsigned long long dup2(float w) {
    unsigned long long r;
    asm("mov.b64 %0, {%1, %1};" : "=l"(r) : "f"(w));
    return r;
}

__global__ void __launch_bounds__(256, 1)
gemm_part_kernel(const float* __restrict__ A, const float* __restrict__ W,
                 float* __restrict__ part, int N)
{
    extern __shared__ float fsm[];
    float (*Hs)[GBK][GBMp] = reinterpret_cast<float (*)[GBK][GBMp]>(fsm);
    float (*Ws)[GBK][GBMp] = reinterpret_cast<float (*)[GBK][GBMp]>(fsm + 2 * GBK * GBMp);

    const int tid = threadIdx.x;
    const int bn = blockIdx.x, bm = blockIdx.y, ks = blockIdx.z;
    const int k0 = ks * GKPS;
    const int lr = tid >> 3, lk = (tid & 7) << 2;
    const float* Ag = A + (size_t)(bm * GBM + lr) * H_ + k0 + lk;
    const float* Wg = W + (size_t)(bn * 128 + lr) * H_ + k0 + lk;
    const int tm = (tid & 15) * 8, tn = (tid >> 4) * 8;

    unsigned long long acc[4][8];
#pragma unroll
    for (int i = 0; i < 4; i++)
#pragma unroll
        for (int j = 0; j < 8; j++) acc[i][j] = 0ull;

    float4 ra[4], rb[4];
    auto LDG = [&](int ch) {
        const float* a = Ag + ch * GBK;
        const float* w = Wg + ch * GBK;
#pragma unroll
        for (int p = 0; p < 4; p++) {
            ra[p] = *reinterpret_cast<const float4*>(a + (size_t)p * 32 * H_);
            rb[p] = *reinterpret_cast<const float4*>(w + (size_t)p * 32 * H_);
        }
    };
    auto STS = [&](int buf) {
#pragma unroll
        for (int p = 0; p < 4; p++) {
            const float* va = reinterpret_cast<const float*>(&ra[p]);
            const float* vb = reinterpret_cast<const float*>(&rb[p]);
            const int m = p * 32 + lr;
#pragma unroll
            for (int q = 0; q < 4; q++) {
                Hs[buf][lk + q][m] = va[q];
                Ws[buf][lk + q][m] = vb[q];
            }
        }
    };
    auto COMPUTE = [&](int buf) {
#pragma unroll 4
        for (int kk = 0; kk < GBK; kk++) {
            ulonglong2 hA = *reinterpret_cast<const ulonglong2*>(&Hs[buf][kk][tm]);
            ulonglong2 hB = *reinterpret_cast<const ulonglong2*>(&Hs[buf][kk][tm + 4]);
            float4 wa = *reinterpret_cast<const float4*>(&Ws[buf][kk][tn]);
            float4 wb = *reinterpret_cast<const float4*>(&Ws[buf][kk][tn + 4]);
            unsigned long long h[4] = { hA.x, hA.y, hB.x, hB.y };
            unsigned long long w[8] = { dup2(wa.x), dup2(wa.y), dup2(wa.z), dup2(wa.w),
                                        dup2(wb.x), dup2(wb.y), dup2(wb.z), dup2(wb.w) };
#pragma unroll
            for (int i = 0; i < 4; i++)
#pragma unroll
                for (int j = 0; j < 8; j++) ffma2(acc[i][j], h[i], w[j]);
        }
    };

    LDG(0); STS(0); LDG(1);
    __syncthreads();
#pragma unroll 1
    for (int ch = 0; ch < GNCH; ch++) {
        const int buf = ch & 1;
        if (ch + 1 < GNCH) STS(buf ^ 1);
        if (ch + 2 < GNCH) LDG(ch + 2);
        COMPUTE(buf);
        __syncthreads();
    }

    float* P = part + (size_t)ks * B_ * N + (size_t)(bm * GBM) * N + bn * 128;
#pragma unroll
    for (int i = 0; i < 4; i++) {
        const int r0 = tm + 2 * i;
        float2 f[8];
#pragma unroll
        for (int j = 0; j < 8; j++) f[j] = *reinterpret_cast<float2*>(&acc[i][j]);
        *reinterpret_cast<float4*>(P + (size_t)r0 * N + tn)           = make_float4(f[0].x, f[1].x, f[2].x, f[3].x);
        *reinterpret_cast<float4*>(P + (size_t)r0 * N + tn + 4)       = make_float4(f[4].x, f[5].x, f[6].x, f[7].x);
        *reinterpret_cast<float4*>(P + (size_t)(r0 + 1) * N + tn)     = make_float4(f[0].y, f[1].y, f[2].y, f[3].y);
        *reinterpret_cast<float4*>(P + (size_t)(r0 + 1) * N + tn + 4) = make_float4(f[4].y, f[5].y, f[6].y, f[7].y);
    }
}

__global__ void combine_o(const float* __restrict__ parto,
                          const float* __restrict__ bp, float* __restrict__ out)
{
    const int idx = blockIdx.x * blockDim.x + threadIdx.x;
    const int b = idx >> 5;
    const int c = (idx & 31) << 2;
    float4 s = *reinterpret_cast<const float4*>(bp + c);
    const size_t off = (size_t)b * C_ + c;
#pragma unroll
    for (int z = 0; z < GKS; z++) {
        float4 p = *reinterpret_cast<const float4*>(parto + (size_t)z * B_ * C_ + off);
        s.x += p.x; s.y += p.y; s.z += p.z; s.w += p.w;
    }
    *reinterpret_cast<float4*>(out + off) = s;
}

// ================= launch =================
extern "C" void kernel_launch(void* const* d_in, const int* in_sizes, int n_in,
                              void* d_out, int out_size)
{
    const float* x   = (const float*)d_in[0];   // [512,256]
    const float* whx = (const float*)d_in[1];   // [1024,1]
    const float* whh = (const float*)d_in[2];   // [1024,1024]
    const float* bh  = (const float*)d_in[3];   // [1024]
    const float* wph = (const float*)d_in[4];   // [128,1024]
    const float* bp  = (const float*)d_in[5];   // [128]
    float* out = (float*)d_out;                 // [512,128]

    float *h, *parto;
    __nv_bfloat16 *wh_hi, *wh_lo, *a_hi, *a_lo;
    cudaGetSymbolAddress((void**)&h,     g_h);
    cudaGetSymbolAddress((void**)&wh_hi, g_whi);
    cudaGetSymbolAddress((void**)&wh_lo, g_wlo);
    cudaGetSymbolAddress((void**)&a_hi,  g_ahi);
    cudaGetSymbolAddress((void**)&a_lo,  g_alo);
    cudaGetSymbolAddress((void**)&parto, g_parto);

    cudaFuncSetAttribute(rnn_step, cudaFuncAttributeMaxDynamicSharedMemorySize, STEP_SMEM);
    const size_t gsmem = (size_t)2 * GBK * GBMp * sizeof(float) * 2;
    cudaFuncSetAttribute(gemm_part_kernel, cudaFuncAttributeMaxDynamicSharedMemorySize, (int)gsmem);

    // one-time: split W_hh into hi/lo bf16
    split_w<<<1024, 256>>>(whh, wh_hi, wh_lo);

    // step 0: h = tanh(x_0 * W_hx^T + b_h)
    init_h<<<512, 256>>>(x, whx, bh, a_hi, a_lo);

    // steps 1..255 on tensor cores (base-ISA mma.sync path)
    const size_t HB = (size_t)B_ * H_;
    for (int t = 1; t < T_; t++) {
        const int ib = (t - 1) & 1, ob = t & 1;
        rnn_step<<<dim3(H_ / BN, B_ / BM), 256, STEP_SMEM>>>(
            a_hi + (size_t)ib * HB, a_lo + (size_t)ib * HB,
            wh_hi, wh_lo, x, whx, bh,
            h, a_hi + (size_t)ob * HB, a_lo + (size_t)ob * HB,
            t, (t == T_ - 1) ? 1 : 0);
    }

    // head: out = h_last @ W_ph^T + b_p
    gemm_part_kernel<<<dim3(1, B_ / GBM, GKS), 256, gsmem>>>(h, wph, parto, C_);
    combine_o<<<(B_ * C_ / 4) / 256, 256>>>(parto, bp, out);
}

// round 10
// speedup vs baseline: 1.5591x; 1.3740x over previous
#include <cuda_runtime.h>
#include <cuda_bf16.h>
#include <math.h>
#include <stdint.h>

// ---------------- problem dims ----------------
#define B_   512
#define T_   256
#define H_   1024
#define C_   128

// ---------------- tiled-block operand layout ----------------
// 64x64 bf16 blocks, k-stride padded to 72 elems (144B rows, conflict-free
// for ldmatrix: rows start at banks 0,4,8,...,28). Blocks stored contiguously
// so one cp.async.bulk fetches a whole (hi,lo) pair.
#define BLK       64
#define KPAD      72
#define BLK_ELEMS (BLK * KPAD)        // 4608
#define BLK_BYTES (BLK_ELEMS * 2)     // 9216
#define NKC       (H_ / BLK)          // 16 k-chunks
#define NBM       (B_ / BLK)          // 8
#define NBN       (H_ / BLK)          // 16
#define NS        5                   // pipeline stages
#define PAIR_BYTES (2 * BLK_BYTES)    // 18432 (hi+lo)
#define STG_BYTES  (2 * PAIR_BYTES)   // 36864 (A pair + W pair)
#define SMEM_STG0  128                // mbarrier region
#define STEP_SMEM  (SMEM_STG0 + NS * STG_BYTES)   // 184448

// ---------------- device scratch (no runtime allocation allowed) ----------------
__device__ float g_h[B_ * H_];
__device__ __align__(128) __nv_bfloat16 g_wt[(size_t)NBN * NKC * 2 * BLK_ELEMS];
__device__ __align__(128) __nv_bfloat16 g_at[2][(size_t)NBM * NKC * 2 * BLK_ELEMS];
__device__ float g_parto[4][B_ * C_];

// ---------------- base-ISA PTX helpers (compute_103-safe) ----------------
__device__ __forceinline__ uint32_t smem_u32(const void* p) {
    uint32_t a;
    asm("{ .reg .u64 t; cvta.to.shared.u64 t, %1; cvt.u32.u64 %0, t; }"
        : "=r"(a) : "l"(p));
    return a;
}
#define MBAR_INIT(a, c) \
    asm volatile("mbarrier.init.shared.b64 [%0], %1;" :: "r"(a), "r"(c) : "memory")
#define MBAR_ARRIVE(a) \
    asm volatile("mbarrier.arrive.shared.b64 _, [%0];" :: "r"(a) : "memory")
#define MBAR_EXPECT_TX(a, n) \
    asm volatile("mbarrier.arrive.expect_tx.shared.b64 _, [%0], %1;" \
                 :: "r"(a), "r"(n) : "memory")
#define MBAR_WAIT(a, ph) do {                                                     \
    uint32_t _m = (a), _p = (ph), _d;                                             \
    asm volatile("{\n\t.reg .pred p;\n\t"                                         \
        "mbarrier.try_wait.parity.acquire.cta.shared::cta.b64 p, [%1], %2;\n\t"   \
        "selp.b32 %0, 1, 0, p;\n\t}" : "=r"(_d) : "r"(_m), "r"(_p) : "memory");   \
    if (!_d) {                                                                     \
        asm volatile("{\n\t.reg .pred P1;\n\tWL_%=:\n\t"                          \
            "mbarrier.try_wait.parity.acquire.cta.shared::cta.b64 P1, [%0], %1, 0x989680;\n\t" \
            "@P1 bra.uni WD_%=;\n\tbra.uni WL_%=;\n\tWD_%=:\n\t}"                 \
            :: "r"(_m), "r"(_p) : "memory");                                      \
    } } while (0)
#define BULK_G2S(dst, src, n, mbar) \
    asm volatile("cp.async.bulk.shared::cluster.global.mbarrier::complete_tx::bytes " \
        "[%0], [%1], %2, [%3];" \
        :: "r"(dst), "l"(src), "r"(n), "r"(mbar) : "memory")

#define LDSM4(r, addr) \
    asm volatile("ldmatrix.sync.aligned.m8n8.x4.shared.b16 {%0,%1,%2,%3}, [%4];" \
        : "=r"((r)[0]), "=r"((r)[1]), "=r"((r)[2]), "=r"((r)[3]) : "r"(addr))

#define MMA16816(c, a, b0, b1) \
    asm volatile("mma.sync.aligned.m16n8k16.row.col.f32.bf16.bf16.f32 " \
        "{%0,%1,%2,%3}, {%4,%5,%6,%7}, {%8,%9}, {%0,%1,%2,%3};" \
        : "+f"((c)[0]), "+f"((c)[1]), "+f"((c)[2]), "+f"((c)[3]) \
        : "r"((a)[0]), "r"((a)[1]), "r"((a)[2]), "r"((a)[3]), "r"(b0), "r"(b1))

// =====================================================================
// per-step kernel: acc = Ahi*Whi^T + Ahi*Wlo^T + Alo*Whi^T (bf16 MMA),
// fused epilogue h = tanh(acc + x_t*W_hx + b_h) -> next-step tiled hi/lo.
// grid (16, 8) = 128 CTAs, 128 threads (4 warps, 32x32 warp tile).
// 5-stage mbarrier pipeline, cp.async.bulk loads, NO __syncthreads in loop.
// =====================================================================
__global__ void __launch_bounds__(128, 1)
rnn_step(const __nv_bfloat16* __restrict__ at_in,
         __nv_bfloat16* __restrict__ at_out,
         const __nv_bfloat16* __restrict__ wt,
         const float* __restrict__ x, const float* __restrict__ whx,
         const float* __restrict__ bh,
         float* __restrict__ hout,
         int t, int last)
{
    extern __shared__ char smem[];
    const uint32_t sb = smem_u32(smem);
    const int tid  = threadIdx.x;
    const int wid  = tid >> 5;
    const int lane = tid & 31;
    const int bn   = blockIdx.x;        // 0..15
    const int bm   = blockIdx.y;        // 0..7
    const int wm   = (wid & 1) * 32;
    const int wn   = (wid >> 1) * 32;

    // mbarriers: full[s] at sb+8s, empty[s] at sb+64+8s
    if (tid == 0) {
#pragma unroll
        for (int s = 0; s < NS; s++) {
            MBAR_INIT(sb + 8 * s, 1);        // full: producer arrive+tx
            MBAR_INIT(sb + 64 + 8 * s, 4);   // empty: 1 arrive per warp
        }
    }
    __syncthreads();

    const __nv_bfloat16* srcA = at_in + (size_t)(bm * NKC) * 2 * BLK_ELEMS;
    const __nv_bfloat16* srcW = wt    + (size_t)(bn * NKC) * 2 * BLK_ELEMS;

    // prologue: arm all 5 stages
    if (tid == 0) {
#pragma unroll
        for (int c0 = 0; c0 < NS; c0++) {
            const uint32_t stg = sb + SMEM_STG0 + c0 * STG_BYTES;
            MBAR_EXPECT_TX(sb + 8 * c0, STG_BYTES);
            BULK_G2S(stg,              srcA + (size_t)c0 * 2 * BLK_ELEMS, PAIR_BYTES, sb + 8 * c0);
            BULK_G2S(stg + PAIR_BYTES, srcW + (size_t)c0 * 2 * BLK_ELEMS, PAIR_BYTES, sb + 8 * c0);
        }
    }

    // -------- epilogue constants prefetch --------
    const int qc = (lane & 3) * 2;
    float ew0[4], ew1[4], eb0[4], eb1[4];
#pragma unroll
    for (int ni = 0; ni < 4; ni++) {
        const int j = bn * BLK + wn + ni * 8 + qc;
        ew0[ni] = whx[j];  ew1[ni] = whx[j + 1];
        eb0[ni] = bh[j];   eb1[ni] = bh[j + 1];
    }
    float exv[2][2];
#pragma unroll
    for (int mi = 0; mi < 2; mi++)
#pragma unroll
        for (int hf = 0; hf < 2; hf++) {
            const int gm = bm * BLK + wm + mi * 16 + (lane >> 2) + hf * 8;
            exv[mi][hf] = x[(size_t)gm * T_ + t];
        }

    float acc[2][4][4];
#pragma unroll
    for (int mi = 0; mi < 2; mi++)
#pragma unroll
        for (int ni = 0; ni < 4; ni++)
#pragma unroll
            for (int q = 0; q < 4; q++) acc[mi][ni][q] = 0.0f;

    const int tdiv8 = lane >> 3;
    const int tmod8 = lane & 7;

    // ---------------- mainloop ----------------
    int s = 0, ph = 0;
#pragma unroll 1
    for (int c = 0; c < NKC; c++) {
        MBAR_WAIT(sb + 8 * s, ph);                  // full[s]
        const uint32_t base = sb + SMEM_STG0 + s * STG_BYTES;
#pragma unroll
        for (int ks = 0; ks < 4; ks++) {
            uint32_t Ah[2][4], Al[2][4], Wh[2][4], Wl[2][4];
#pragma unroll
            for (int mi = 0; mi < 2; mi++) {
                const int row = wm + mi * 16 + ((tdiv8 & 1) << 3) + tmod8;
                const int col = ks * 16 + ((tdiv8 >> 1) << 3);
                const uint32_t off = base + (uint32_t)(row * KPAD + col) * 2;
                LDSM4(Ah[mi], off);                     // A hi
                LDSM4(Al[mi], off + BLK_BYTES);         // A lo
            }
#pragma unroll
            for (int np = 0; np < 2; np++) {
                const int row = wn + np * 16 + ((tdiv8 >> 1) << 3) + tmod8;
                const int col = ks * 16 + ((tdiv8 & 1) << 3);
                const uint32_t off = base + PAIR_BYTES + (uint32_t)(row * KPAD + col) * 2;
                LDSM4(Wh[np], off);                     // W hi
                LDSM4(Wl[np], off + BLK_BYTES);         // W lo
            }
#pragma unroll
            for (int p = 0; p < 3; p++) {
                uint32_t (*A)[4] = (p == 2) ? Al : Ah;
                uint32_t (*W)[4] = (p == 1) ? Wl : Wh;
#pragma unroll
                for (int mi = 0; mi < 2; mi++)
#pragma unroll
                    for (int ni = 0; ni < 4; ni++) {
                        const int np = ni >> 1, hf = (ni & 1) * 2;
                        MMA16816(acc[mi][ni], A[mi], W[np][hf], W[np][hf + 1]);
                    }
            }
        }
        if (lane == 0) MBAR_ARRIVE(sb + 64 + 8 * s);    // empty[s], 1/warp
        if (tid == 0 && c + NS < NKC) {
            MBAR_WAIT(sb + 64 + 8 * s, ph);             // all warps done with s
            MBAR_EXPECT_TX(sb + 8 * s, STG_BYTES);
            const int c2 = c + NS;
            BULK_G2S(base,              srcA + (size_t)c2 * 2 * BLK_ELEMS, PAIR_BYTES, sb + 8 * s);
            BULK_G2S(base + PAIR_BYTES, srcW + (size_t)c2 * 2 * BLK_ELEMS, PAIR_BYTES, sb + 8 * s);
        }
        s++; if (s == NS) { s = 0; ph ^= 1; }
    }

    // ---------------- fused epilogue -> tiled A blocks for next step ----------------
    __nv_bfloat16* aout_hi = at_out + ((size_t)(bm * NKC + bn) * 2) * BLK_ELEMS;
    __nv_bfloat16* aout_lo = aout_hi + BLK_ELEMS;
#pragma unroll
    for (int ni = 0; ni < 4; ni++) {
        const int jl = wn + ni * 8 + qc;          // 0..63 within block
        const int j  = bn * BLK + jl;
#pragma unroll
        for (int mi = 0; mi < 2; mi++) {
#pragma unroll
            for (int hf = 0; hf < 2; hf++) {
                const int m  = wm + mi * 16 + (lane >> 2) + hf * 8;
                const int gm = bm * BLK + m;
                const float xv = exv[mi][hf];
                const float c0 = acc[mi][ni][hf * 2];
                const float c1 = acc[mi][ni][hf * 2 + 1];
                const float h0 = tanhf(fmaf(xv, ew0[ni], eb0[ni]) + c0);
                const float h1 = tanhf(fmaf(xv, ew1[ni], eb1[ni]) + c1);
                const __nv_bfloat16 h0h = __float2bfloat16(h0);
                const __nv_bfloat16 h1h = __float2bfloat16(h1);
                const int idx = m * KPAD + jl;
                __nv_bfloat162 hi2; hi2.x = h0h; hi2.y = h1h;
                *reinterpret_cast<__nv_bfloat162*>(aout_hi + idx) = hi2;
                __nv_bfloat162 lo2;
                lo2.x = __float2bfloat16(h0 - __bfloat162float(h0h));
                lo2.y = __float2bfloat16(h1 - __bfloat162float(h1h));
                *reinterpret_cast<__nv_bfloat162*>(aout_lo + idx) = lo2;
                if (last) {
                    float2 f2; f2.x = h0; f2.y = h1;
                    *reinterpret_cast<float2*>(hout + (size_t)gm * H_ + j) = f2;
                }
            }
        }
    }
}

// ================= one-time helpers =================
__global__ void split_w(const float* __restrict__ w, __nv_bfloat16* __restrict__ wt)
{
    const int i = blockIdx.x * blockDim.x + threadIdx.x;   // 1M elements
    const int n = i >> 10, k = i & 1023;
    const float v = w[i];
    const __nv_bfloat16 h = __float2bfloat16(v);
    const __nv_bfloat16 l = __float2bfloat16(v - __bfloat162float(h));
    const size_t base = ((size_t)((n >> 6) * NKC + (k >> 6)) * 2) * BLK_ELEMS
                      + (n & 63) * KPAD + (k & 63);
    wt[base] = h;
    wt[base + BLK_ELEMS] = l;
}

__global__ void init_h(const float* __restrict__ x, const float* __restrict__ whx,
                       const float* __restrict__ bh, __nv_bfloat16* __restrict__ at0)
{
    const int idx = blockIdx.x * blockDim.x + threadIdx.x;  // 512*1024
    const int b = idx >> 10, j = idx & 1023;
    const float hs = tanhf(fmaf(x[(size_t)b * T_], whx[j], bh[j]));
    const __nv_bfloat16 hb = __float2bfloat16(hs);
    const size_t base = ((size_t)((b >> 6) * NKC + (j >> 6)) * 2) * BLK_ELEMS
                      + (b & 63) * KPAD + (j & 63);
    at0[base] = hb;
    at0[base + BLK_ELEMS] = __float2bfloat16(hs - __bfloat162float(hb));
}

// ================= head GEMM (proven SIMT split-K, N=128) =================
#define GBM   128
#define GBK   32
#define GBMp  132
#define GKS   4
#define GKPS  (H_ / GKS)
#define GNCH  (GKPS / GBK)

__device__ __forceinline__ void ffma2(unsigned long long& d,
                                      unsigned long long a, unsigned long long b) {
    asm("fma.rn.f32x2 %0, %1, %2, %0;" : "+l"(d) : "l"(a), "l"(b));
}
__device__ __forceinline__ unsigned long long dup2(float w) {
    unsigned long long r;
    asm("mov.b64 %0, {%1, %1};" : "=l"(r) : "f"(w));
    return r;
}

__global__ void __launch_bounds__(256, 1)
gemm_part_kernel(const float* __restrict__ A, const float* __restrict__ W,
                 float* __restrict__ part, int N)
{
    extern __shared__ float fsm[];
    float (*Hs)[GBK][GBMp] = reinterpret_cast<float (*)[GBK][GBMp]>(fsm);
    float (*Ws)[GBK][GBMp] = reinterpret_cast<float (*)[GBK][GBMp]>(fsm + 2 * GBK * GBMp);

    const int tid = threadIdx.x;
    const int bn = blockIdx.x, bm = blockIdx.y, ks = blockIdx.z;
    const int k0 = ks * GKPS;
    const int lr = tid >> 3, lk = (tid & 7) << 2;
    const float* Ag = A + (size_t)(bm * GBM + lr) * H_ + k0 + lk;
    const float* Wg = W + (size_t)(bn * 128 + lr) * H_ + k0 + lk;
    const int tm = (tid & 15) * 8, tn = (tid >> 4) * 8;

    unsigned long long acc[4][8];
#pragma unroll
    for (int i = 0; i < 4; i++)
#pragma unroll
        for (int j = 0; j < 8; j++) acc[i][j] = 0ull;

    float4 ra[4], rb[4];
    auto LDG = [&](int ch) {
        const float* a = Ag + ch * GBK;
        const float* w = Wg + ch * GBK;
#pragma unroll
        for (int p = 0; p < 4; p++) {
            ra[p] = *reinterpret_cast<const float4*>(a + (size_t)p * 32 * H_);
            rb[p] = *reinterpret_cast<const float4*>(w + (size_t)p * 32 * H_);
        }
    };
    auto STS = [&](int buf) {
#pragma unroll
        for (int p = 0; p < 4; p++) {
            const float* va = reinterpret_cast<const float*>(&ra[p]);
            const float* vb = reinterpret_cast<const float*>(&rb[p]);
            const int m = p * 32 + lr;
#pragma unroll
            for (int q = 0; q < 4; q++) {
                Hs[buf][lk + q][m] = va[q];
                Ws[buf][lk + q][m] = vb[q];
            }
        }
    };
    auto COMPUTE = [&](int buf) {
#pragma unroll 4
        for (int kk = 0; kk < GBK; kk++) {
            ulonglong2 hA = *reinterpret_cast<const ulonglong2*>(&Hs[buf][kk][tm]);
            ulonglong2 hB = *reinterpret_cast<const ulonglong2*>(&Hs[buf][kk][tm + 4]);
            float4 wa = *reinterpret_cast<const float4*>(&Ws[buf][kk][tn]);
            float4 wb = *reinterpret_cast<const float4*>(&Ws[buf][kk][tn + 4]);
            unsigned long long h[4] = { hA.x, hA.y, hB.x, hB.y };
            unsigned long long w[8] = { dup2(wa.x), dup2(wa.y), dup2(wa.z), dup2(wa.w),
                                        dup2(wb.x), dup2(wb.y), dup2(wb.z), dup2(wb.w) };
#pragma unroll
            for (int i = 0; i < 4; i++)
#pragma unroll
                for (int j = 0; j < 8; j++) ffma2(acc[i][j], h[i], w[j]);
        }
    };

    LDG(0); STS(0); LDG(1);
    __syncthreads();
#pragma unroll 1
    for (int ch = 0; ch < GNCH; ch++) {
        const int buf = ch & 1;
        if (ch + 1 < GNCH) STS(buf ^ 1);
        if (ch + 2 < GNCH) LDG(ch + 2);
        COMPUTE(buf);
        __syncthreads();
    }

    float* P = part + (size_t)ks * B_ * N + (size_t)(bm * GBM) * N + bn * 128;
#pragma unroll
    for (int i = 0; i < 4; i++) {
        const int r0 = tm + 2 * i;
        float2 f[8];
#pragma unroll
        for (int j = 0; j < 8; j++) f[j] = *reinterpret_cast<float2*>(&acc[i][j]);
        *reinterpret_cast<float4*>(P + (size_t)r0 * N + tn)           = make_float4(f[0].x, f[1].x, f[2].x, f[3].x);
        *reinterpret_cast<float4*>(P + (size_t)r0 * N + tn + 4)       = make_float4(f[4].x, f[5].x, f[6].x, f[7].x);
        *reinterpret_cast<float4*>(P + (size_t)(r0 + 1) * N + tn)     = make_float4(f[0].y, f[1].y, f[2].y, f[3].y);
        *reinterpret_cast<float4*>(P + (size_t)(r0 + 1) * N + tn + 4) = make_float4(f[4].y, f[5].y, f[6].y, f[7].y);
    }
}

__global__ void combine_o(const float* __restrict__ parto,
                          const float* __restrict__ bp, float* __restrict__ out)
{
    const int idx = blockIdx.x * blockDim.x + threadIdx.x;
    const int b = idx >> 5;
    const int c = (idx & 31) << 2;
    float4 s = *reinterpret_cast<const float4*>(bp + c);
    const size_t off = (size_t)b * C_ + c;
#pragma unroll
    for (int z = 0; z < GKS; z++) {
        float4 p = *reinterpret_cast<const float4*>(parto + (size_t)z * B_ * C_ + off);
        s.x += p.x; s.y += p.y; s.z += p.z; s.w += p.w;
    }
    *reinterpret_cast<float4*>(out + off) = s;
}

// ================= launch =================
extern "C" void kernel_launch(void* const* d_in, const int* in_sizes, int n_in,
                              void* d_out, int out_size)
{
    const float* x   = (const float*)d_in[0];   // [512,256]
    const float* whx = (const float*)d_in[1];   // [1024,1]
    const float* whh = (const float*)d_in[2];   // [1024,1024]
    const float* bh  = (const float*)d_in[3];   // [1024]
    const float* wph = (const float*)d_in[4];   // [128,1024]
    const float* bp  = (const float*)d_in[5];   // [128]
    float* out = (float*)d_out;                 // [512,128]

    float *h, *parto;
    __nv_bfloat16 *wt, *at;
    cudaGetSymbolAddress((void**)&h,     g_h);
    cudaGetSymbolAddress((void**)&wt,    g_wt);
    cudaGetSymbolAddress((void**)&at,    g_at);
    cudaGetSymbolAddress((void**)&parto, g_parto);
    const size_t ABUF = (size_t)NBM * NKC * 2 * BLK_ELEMS;

    cudaFuncSetAttribute(rnn_step, cudaFuncAttributeMaxDynamicSharedMemorySize, STEP_SMEM);
    const size_t gsmem = (size_t)2 * GBK * GBMp * sizeof(float) * 2;
    cudaFuncSetAttribute(gemm_part_kernel, cudaFuncAttributeMaxDynamicSharedMemorySize, (int)gsmem);

    // one-time: split W_hh into tiled hi/lo blocks
    split_w<<<4096, 256>>>(whh, wt);

    // step 0: h = tanh(x_0 * W_hx^T + b_h) -> tiled A buf 0
    init_h<<<2048, 256>>>(x, whx, bh, at);

    // steps 1..255 on tensor cores
    for (int t = 1; t < T_; t++) {
        const int ib = (t - 1) & 1, ob = t & 1;
        rnn_step<<<dim3(NBN, NBM), 128, STEP_SMEM>>>(
            at + (size_t)ib * ABUF, at + (size_t)ob * ABUF, wt,
            x, whx, bh, h, t, (t == T_ - 1) ? 1 : 0);
    }

    // head: out = h_last @ W_ph^T + b_p
    gemm_part_kernel<<<dim3(1, B_ / GBM, GKS), 256, gsmem>>>(h, wph, parto, C_);
    combine_o<<<(B_ * C_ / 4) / 256, 256>>>(parto, bp, out);
}

// round 11
// speedup vs baseline: 1.7043x; 1.0931x over previous
#include <cuda_runtime.h>
#include <cuda_bf16.h>
#include <math.h>
#include <stdint.h>

// ---------------- problem dims ----------------
#define B_   512
#define T_   256
#define H_   1024
#define C_   128

// ---------------- tiled-block operand layout ----------------
// 64x64 bf16 blocks, k-stride padded to 72 elems (144B rows, conflict-free
// for ldmatrix). Blocks stored contiguously so one cp.async.bulk fetches a
// whole (hi,lo) pair.
#define BLK       64
#define KPAD      72
#define BLK_ELEMS (BLK * KPAD)        // 4608
#define BLK_BYTES (BLK_ELEMS * 2)     // 9216
#define NKC       (H_ / BLK)          // 16 k-chunks
#define NBM       (B_ / BLK)          // 8
#define NBN       (H_ / BLK)          // 16
#define NS        5                   // pipeline stages
#define PAIR_BYTES (2 * BLK_BYTES)    // 18432 (hi+lo)
#define STG_BYTES  (2 * PAIR_BYTES)   // 36864 (A pair + W pair)
#define SMEM_STG0  128                // mbarrier region
#define STEP_SMEM  (SMEM_STG0 + NS * STG_BYTES)   // 184448

// ---------------- device scratch (no runtime allocation allowed) ----------------
__device__ float g_h[B_ * H_];
__device__ __align__(128) __nv_bfloat16 g_wt[(size_t)NBN * NKC * 2 * BLK_ELEMS];
__device__ __align__(128) __nv_bfloat16 g_at[2][(size_t)NBM * NKC * 2 * BLK_ELEMS];
__device__ float g_parto[4][B_ * C_];

// ---------------- base-ISA PTX helpers (compute_103-safe) ----------------
__device__ __forceinline__ uint32_t smem_u32(const void* p) {
    uint32_t a;
    asm("{ .reg .u64 t; cvta.to.shared.u64 t, %1; cvt.u32.u64 %0, t; }"
        : "=r"(a) : "l"(p));
    return a;
}
#define MBAR_INIT(a, c) \
    asm volatile("mbarrier.init.shared.b64 [%0], %1;" :: "r"(a), "r"(c) : "memory")
#define MBAR_ARRIVE(a) \
    asm volatile("mbarrier.arrive.shared.b64 _, [%0];" :: "r"(a) : "memory")
#define MBAR_EXPECT_TX(a, n) \
    asm volatile("mbarrier.arrive.expect_tx.shared.b64 _, [%0], %1;" \
                 :: "r"(a), "r"(n) : "memory")
#define MBAR_WAIT(a, ph) do {                                                     \
    uint32_t _m = (a), _p = (ph), _d;                                             \
    asm volatile("{\n\t.reg .pred p;\n\t"                                         \
        "mbarrier.try_wait.parity.acquire.cta.shared::cta.b64 p, [%1], %2;\n\t"   \
        "selp.b32 %0, 1, 0, p;\n\t}" : "=r"(_d) : "r"(_m), "r"(_p) : "memory");   \
    if (!_d) {                                                                     \
        asm volatile("{\n\t.reg .pred P1;\n\tWL_%=:\n\t"                          \
            "mbarrier.try_wait.parity.acquire.cta.shared::cta.b64 P1, [%0], %1, 0x989680;\n\t" \
            "@P1 bra.uni WD_%=;\n\tbra.uni WL_%=;\n\tWD_%=:\n\t}"                 \
            :: "r"(_m), "r"(_p) : "memory");                                      \
    } } while (0)
#define BULK_G2S(dst, src, n, mbar) \
    asm volatile("cp.async.bulk.shared::cluster.global.mbarrier::complete_tx::bytes " \
        "[%0], [%1], %2, [%3];" \
        :: "r"(dst), "l"(src), "r"(n), "r"(mbar) : "memory")

#define LDSM4(r, addr) \
    asm volatile("ldmatrix.sync.aligned.m8n8.x4.shared.b16 {%0,%1,%2,%3}, [%4];" \
        : "=r"((r)[0]), "=r"((r)[1]), "=r"((r)[2]), "=r"((r)[3]) : "r"(addr))

#define MMA16816(c, a, b0, b1) \
    asm volatile("mma.sync.aligned.m16n8k16.row.col.f32.bf16.bf16.f32 " \
        "{%0,%1,%2,%3}, {%4,%5,%6,%7}, {%8,%9}, {%0,%1,%2,%3};" \
        : "+f"((c)[0]), "+f"((c)[1]), "+f"((c)[2]), "+f"((c)[3]) \
        : "r"((a)[0]), "r"((a)[1]), "r"((a)[2]), "r"((a)[3]), "r"(b0), "r"(b1))

// =====================================================================
// per-step kernel: acc = Ahi*Whi^T + Ahi*Wlo^T + Alo*Whi^T (bf16 MMA),
// fused epilogue h = tanh(acc + x_t*W_hx + b_h) -> next-step tiled hi/lo.
// grid (16, 8) = 128 CTAs, 256 threads (8 warps, warp tile 32x16: 2/SMSP).
// 5-stage mbarrier pipeline, cp.async.bulk loads, NO __syncthreads in loop.
// =====================================================================
__global__ void __launch_bounds__(256, 1)
rnn_step(const __nv_bfloat16* __restrict__ at_in,
         __nv_bfloat16* __restrict__ at_out,
         const __nv_bfloat16* __restrict__ wt,
         const float* __restrict__ x, const float* __restrict__ whx,
         const float* __restrict__ bh,
         float* __restrict__ hout,
         int t, int last)
{
    extern __shared__ char smem[];
    const uint32_t sb = smem_u32(smem);
    const int tid  = threadIdx.x;
    const int wid  = tid >> 5;
    const int lane = tid & 31;
    const int bn   = blockIdx.x;        // 0..15
    const int bm   = blockIdx.y;        // 0..7
    const int wm   = (wid & 1) * 32;    // 2 m-warps
    const int wn   = (wid >> 1) * 16;   // 4 n-warps

    // mbarriers: full[s] at sb+8s, empty[s] at sb+64+8s
    if (tid == 0) {
#pragma unroll
        for (int s = 0; s < NS; s++) {
            MBAR_INIT(sb + 8 * s, 1);        // full: producer arrive+tx
            MBAR_INIT(sb + 64 + 8 * s, 8);   // empty: 1 arrive per warp
        }
    }
    __syncthreads();

    const __nv_bfloat16* srcA = at_in + (size_t)(bm * NKC) * 2 * BLK_ELEMS;
    const __nv_bfloat16* srcW = wt    + (size_t)(bn * NKC) * 2 * BLK_ELEMS;

    // prologue: arm all 5 stages
    if (tid == 0) {
#pragma unroll
        for (int c0 = 0; c0 < NS; c0++) {
            const uint32_t stg = sb + SMEM_STG0 + c0 * STG_BYTES;
            MBAR_EXPECT_TX(sb + 8 * c0, STG_BYTES);
            BULK_G2S(stg,              srcA + (size_t)c0 * 2 * BLK_ELEMS, PAIR_BYTES, sb + 8 * c0);
            BULK_G2S(stg + PAIR_BYTES, srcW + (size_t)c0 * 2 * BLK_ELEMS, PAIR_BYTES, sb + 8 * c0);
        }
    }

    // -------- epilogue constants prefetch --------
    const int qc = (lane & 3) * 2;
    float ew0[2], ew1[2], eb0[2], eb1[2];
#pragma unroll
    for (int ni = 0; ni < 2; ni++) {
        const int j = bn * BLK + wn + ni * 8 + qc;
        ew0[ni] = whx[j];  ew1[ni] = whx[j + 1];
        eb0[ni] = bh[j];   eb1[ni] = bh[j + 1];
    }
    float exv[2][2];
#pragma unroll
    for (int mi = 0; mi < 2; mi++)
#pragma unroll
        for (int hf = 0; hf < 2; hf++) {
            const int gm = bm * BLK + wm + mi * 16 + (lane >> 2) + hf * 8;
            exv[mi][hf] = x[(size_t)gm * T_ + t];
        }

    float acc[2][2][4];                 // [mi][ni][quad]
#pragma unroll
    for (int mi = 0; mi < 2; mi++)
#pragma unroll
        for (int ni = 0; ni < 2; ni++)
#pragma unroll
            for (int q = 0; q < 4; q++) acc[mi][ni][q] = 0.0f;

    const int tdiv8 = lane >> 3;
    const int tmod8 = lane & 7;
    const int arow = wm + ((tdiv8 & 1) << 3) + tmod8;   // A ldmatrix row base
    const int wrow = wn + ((tdiv8 >> 1) << 3) + tmod8;  // W ldmatrix row

    // ---------------- mainloop ----------------
    int s = 0, ph = 0;
#pragma unroll 1
    for (int c = 0; c < NKC; c++) {
        MBAR_WAIT(sb + 8 * s, ph);                  // full[s]
        const uint32_t base = sb + SMEM_STG0 + s * STG_BYTES;
#pragma unroll
        for (int ks = 0; ks < 4; ks++) {
            uint32_t Ah[2][4], Al[2][4], Wh[4], Wl[4];
#pragma unroll
            for (int mi = 0; mi < 2; mi++) {
                const int row = arow + mi * 16;
                const int col = ks * 16 + ((tdiv8 >> 1) << 3);
                const uint32_t off = base + (uint32_t)(row * KPAD + col) * 2;
                LDSM4(Ah[mi], off);                     // A hi
                LDSM4(Al[mi], off + BLK_BYTES);         // A lo
            }
            {
                const int col = ks * 16 + ((tdiv8 & 1) << 3);
                const uint32_t off = base + PAIR_BYTES + (uint32_t)(wrow * KPAD + col) * 2;
                LDSM4(Wh, off);                         // W hi
                LDSM4(Wl, off + BLK_BYTES);             // W lo
            }
#pragma unroll
            for (int p = 0; p < 3; p++) {
                uint32_t (*A)[4] = (p == 2) ? Al : Ah;
                uint32_t* W      = (p == 1) ? Wl : Wh;
#pragma unroll
                for (int mi = 0; mi < 2; mi++)
#pragma unroll
                    for (int ni = 0; ni < 2; ni++)
                        MMA16816(acc[mi][ni], A[mi], W[ni * 2], W[ni * 2 + 1]);
            }
        }
        if (lane == 0) MBAR_ARRIVE(sb + 64 + 8 * s);    // empty[s], 1/warp
        if (tid == 0 && c + NS < NKC) {
            MBAR_WAIT(sb + 64 + 8 * s, ph);             // all warps done with s
            MBAR_EXPECT_TX(sb + 8 * s, STG_BYTES);
            const int c2 = c + NS;
            BULK_G2S(base,              srcA + (size_t)c2 * 2 * BLK_ELEMS, PAIR_BYTES, sb + 8 * s);
            BULK_G2S(base + PAIR_BYTES, srcW + (size_t)c2 * 2 * BLK_ELEMS, PAIR_BYTES, sb + 8 * s);
        }
        s++; if (s == NS) { s = 0; ph ^= 1; }
    }

    // ---------------- fused epilogue -> tiled A blocks for next step ----------------
    __nv_bfloat16* aout_hi = at_out + ((size_t)(bm * NKC + bn) * 2) * BLK_ELEMS;
    __nv_bfloat16* aout_lo = aout_hi + BLK_ELEMS;
#pragma unroll
    for (int ni = 0; ni < 2; ni++) {
        const int jl = wn + ni * 8 + qc;          // 0..63 within block
        const int j  = bn * BLK + jl;
#pragma unroll
        for (int mi = 0; mi < 2; mi++) {
#pragma unroll
            for (int hf = 0; hf < 2; hf++) {
                const int m  = wm + mi * 16 + (lane >> 2) + hf * 8;
                const int gm = bm * BLK + m;
                const float xv = exv[mi][hf];
                const float c0 = acc[mi][ni][hf * 2];
                const float c1 = acc[mi][ni][hf * 2 + 1];
                const float h0 = tanhf(fmaf(xv, ew0[ni], eb0[ni]) + c0);
                const float h1 = tanhf(fmaf(xv, ew1[ni], eb1[ni]) + c1);
                const __nv_bfloat16 h0h = __float2bfloat16(h0);
                const __nv_bfloat16 h1h = __float2bfloat16(h1);
                const int idx = m * KPAD + jl;
                __nv_bfloat162 hi2; hi2.x = h0h; hi2.y = h1h;
                *reinterpret_cast<__nv_bfloat162*>(aout_hi + idx) = hi2;
                __nv_bfloat162 lo2;
                lo2.x = __float2bfloat16(h0 - __bfloat162float(h0h));
                lo2.y = __float2bfloat16(h1 - __bfloat162float(h1h));
                *reinterpret_cast<__nv_bfloat162*>(aout_lo + idx) = lo2;
                if (last) {
                    float2 f2; f2.x = h0; f2.y = h1;
                    *reinterpret_cast<float2*>(hout + (size_t)gm * H_ + j) = f2;
                }
            }
        }
    }
}

// ================= one-time helpers =================
__global__ void split_w(const float* __restrict__ w, __nv_bfloat16* __restrict__ wt)
{
    const int i = blockIdx.x * blockDim.x + threadIdx.x;   // 1M elements
    const int n = i >> 10, k = i & 1023;
    const float v = w[i];
    const __nv_bfloat16 h = __float2bfloat16(v);
    const __nv_bfloat16 l = __float2bfloat16(v - __bfloat162float(h));
    const size_t base = ((size_t)((n >> 6) * NKC + (k >> 6)) * 2) * BLK_ELEMS
                      + (n & 63) * KPAD + (k & 63);
    wt[base] = h;
    wt[base + BLK_ELEMS] = l;
}

__global__ void init_h(const float* __restrict__ x, const float* __restrict__ whx,
                       const float* __restrict__ bh, __nv_bfloat16* __restrict__ at0)
{
    const int idx = blockIdx.x * blockDim.x + threadIdx.x;  // 512*1024
    const int b = idx >> 10, j = idx & 1023;
    const float hs = tanhf(fmaf(x[(size_t)b * T_], whx[j], bh[j]));
    const __nv_bfloat16 hb = __float2bfloat16(hs);
    const size_t base = ((size_t)((b >> 6) * NKC + (j >> 6)) * 2) * BLK_ELEMS
                      + (b & 63) * KPAD + (j & 63);
    at0[base] = hb;
    at0[base + BLK_ELEMS] = __float2bfloat16(hs - __bfloat162float(hb));
}

// ================= head GEMM (proven SIMT split-K, N=128) =================
#define GBM   128
#define GBK   32
#define GBMp  132
#define GKS   4
#define GKPS  (H_ / GKS)
#define GNCH  (GKPS / GBK)

__device__ __forceinline__ void ffma2(unsigned long long& d,
                                      unsigned long long a, unsigned long long b) {
    asm("fma.rn.f32x2 %0, %1, %2, %0;" : "+l"(d) : "l"(a), "l"(b));
}
__device__ __forceinline__ unsigned long long dup2(float w) {
    unsigned long long r;
    asm("mov.b64 %0, {%1, %1};" : "=l"(r) : "f"(w));
    return r;
}

__global__ void __launch_bounds__(256, 1)
gemm_part_kernel(const float* __restrict__ A, const float* __restrict__ W,
                 float* __restrict__ part, int N)
{
    extern __shared__ float fsm[];
    float (*Hs)[GBK][GBMp] = reinterpret_cast<float (*)[GBK][GBMp]>(fsm);
    float (*Ws)[GBK][GBMp] = reinterpret_cast<float (*)[GBK][GBMp]>(fsm + 2 * GBK * GBMp);

    const int tid = threadIdx.x;
    const int bn = blockIdx.x, bm = blockIdx.y, ks = blockIdx.z;
    const int k0 = ks * GKPS;
    const int lr = tid >> 3, lk = (tid & 7) << 2;
    const float* Ag = A + (size_t)(bm * GBM + lr) * H_ + k0 + lk;
    const float* Wg = W + (size_t)(bn * 128 + lr) * H_ + k0 + lk;
    const int tm = (tid & 15) * 8, tn = (tid >> 4) * 8;

    unsigned long long acc[4][8];
#pragma unroll
    for (int i = 0; i < 4; i++)
#pragma unroll
        for (int j = 0; j < 8; j++) acc[i][j] = 0ull;

    float4 ra[4], rb[4];
    auto LDG = [&](int ch) {
        const float* a = Ag + ch * GBK;
        const float* w = Wg + ch * GBK;
#pragma unroll
        for (int p = 0; p < 4; p++) {
            ra[p] = *reinterpret_cast<const float4*>(a + (size_t)p * 32 * H_);
            rb[p] = *reinterpret_cast<const float4*>(w + (size_t)p * 32 * H_);
        }
    };
    auto STS = [&](int buf) {
#pragma unroll
        for (int p = 0; p < 4; p++) {
            const float* va = reinterpret_cast<const float*>(&ra[p]);
            const float* vb = reinterpret_cast<const float*>(&rb[p]);
            const int m = p * 32 + lr;
#pragma unroll
            for (int q = 0; q < 4; q++) {
                Hs[buf][lk + q][m] = va[q];
                Ws[buf][lk + q][m] = vb[q];
            }
        }
    };
    auto COMPUTE = [&](int buf) {
#pragma unroll 4
        for (int kk = 0; kk < GBK; kk++) {
            ulonglong2 hA = *reinterpret_cast<const ulonglong2*>(&Hs[buf][kk][tm]);
            ulonglong2 hB = *reinterpret_cast<const ulonglong2*>(&Hs[buf][kk][tm + 4]);
            float4 wa = *reinterpret_cast<const float4*>(&Ws[buf][kk][tn]);
            float4 wb = *reinterpret_cast<const float4*>(&Ws[buf][kk][tn + 4]);
            unsigned long long h[4] = { hA.x, hA.y, hB.x, hB.y };
            unsigned long long w[8] = { dup2(wa.x), dup2(wa.y), dup2(wa.z), dup2(wa.w),
                                        dup2(wb.x), dup2(wb.y), dup2(wb.z), dup2(wb.w) };
#pragma unroll
            for (int i = 0; i < 4; i++)
#pragma unroll
                for (int j = 0; j < 8; j++) ffma2(acc[i][j], h[i], w[j]);
        }
    };

    LDG(0); STS(0); LDG(1);
    __syncthreads();
#pragma unroll 1
    for (int ch = 0; ch < GNCH; ch++) {
        const int buf = ch & 1;
        if (ch + 1 < GNCH) STS(buf ^ 1);
        if (ch + 2 < GNCH) LDG(ch + 2);
        COMPUTE(buf);
        __syncthreads();
    }

    float* P = part + (size_t)ks * B_ * N + (size_t)(bm * GBM) * N + bn * 128;
#pragma unroll
    for (int i = 0; i < 4; i++) {
        const int r0 = tm + 2 * i;
        float2 f[8];
#pragma unroll
        for (int j = 0; j < 8; j++) f[j] = *reinterpret_cast<float2*>(&acc[i][j]);
        *reinterpret_cast<float4*>(P + (size_t)r0 * N + tn)           = make_float4(f[0].x, f[1].x, f[2].x, f[3].x);
        *reinterpret_cast<float4*>(P + (size_t)r0 * N + tn + 4)       = make_float4(f[4].x, f[5].x, f[6].x, f[7].x);
        *reinterpret_cast<float4*>(P + (size_t)(r0 + 1) * N + tn)     = make_float4(f[0].y, f[1].y, f[2].y, f[3].y);
        *reinterpret_cast<float4*>(P + (size_t)(r0 + 1) * N + tn + 4) = make_float4(f[4].y, f[5].y, f[6].y, f[7].y);
    }
}

__global__ void combine_o(const float* __restrict__ parto,
                          const float* __restrict__ bp, float* __restrict__ out)
{
    const int idx = blockIdx.x * blockDim.x + threadIdx.x;
    const int b = idx >> 5;
    const int c = (idx & 31) << 2;
    float4 s = *reinterpret_cast<const float4*>(bp + c);
    const size_t off = (size_t)b * C_ + c;
#pragma unroll
    for (int z = 0; z < GKS; z++) {
        float4 p = *reinterpret_cast<const float4*>(parto + (size_t)z * B_ * C_ + off);
        s.x += p.x; s.y += p.y; s.z += p.z; s.w += p.w;
    }
    *reinterpret_cast<float4*>(out + off) = s;
}

// ================= launch =================
extern "C" void kernel_launch(void* const* d_in, const int* in_sizes, int n_in,
                              void* d_out, int out_size)
{
    const float* x   = (const float*)d_in[0];   // [512,256]
    const float* whx = (const float*)d_in[1];   // [1024,1]
    const float* whh = (const float*)d_in[2];   // [1024,1024]
    const float* bh  = (const float*)d_in[3];   // [1024]
    const float* wph = (const float*)d_in[4];   // [128,1024]
    const float* bp  = (const float*)d_in[5];   // [128]
    float* out = (float*)d_out;                 // [512,128]

    float *h, *parto;
    __nv_bfloat16 *wt, *at;
    cudaGetSymbolAddress((void**)&h,     g_h);
    cudaGetSymbolAddress((void**)&wt,    g_wt);
    cudaGetSymbolAddress((void**)&at,    g_at);
    cudaGetSymbolAddress((void**)&parto, g_parto);
    const size_t ABUF = (size_t)NBM * NKC * 2 * BLK_ELEMS;

    cudaFuncSetAttribute(rnn_step, cudaFuncAttributeMaxDynamicSharedMemorySize, STEP_SMEM);
    const size_t gsmem = (size_t)2 * GBK * GBMp * sizeof(float) * 2;
    cudaFuncSetAttribute(gemm_part_kernel, cudaFuncAttributeMaxDynamicSharedMemorySize, (int)gsmem);

    // one-time: split W_hh into tiled hi/lo blocks
    split_w<<<4096, 256>>>(whh, wt);

    // step 0: h = tanh(x_0 * W_hx^T + b_h) -> tiled A buf 0
    init_h<<<2048, 256>>>(x, whx, bh, at);

    // steps 1..255 on tensor cores
    for (int t = 1; t < T_; t++) {
        const int ib = (t - 1) & 1, ob = t & 1;
        rnn_step<<<dim3(NBN, NBM), 256, STEP_SMEM>>>(
            at + (size_t)ib * ABUF, at + (size_t)ob * ABUF, wt,
            x, whx, bh, h, t, (t == T_ - 1) ? 1 : 0);
    }

    // head: out = h_last @ W_ph^T + b_p
    gemm_part_kernel<<<dim3(1, B_ / GBM, GKS), 256, gsmem>>>(h, wph, parto, C_);
    combine_o<<<(B_ * C_ / 4) / 256, 256>>>(parto, bp, out);
}

// round 12
// speedup vs baseline: 1.7691x; 1.0380x over previous
#include <cuda_runtime.h>
#include <cuda_bf16.h>
#include <math.h>
#include <stdint.h>

// ---------------- problem dims ----------------
#define B_   512
#define T_   256
#define H_   1024
#define C_   128

// ---------------- tiled-block operand layout ----------------
#define BLK       64
#define KPAD      72
#define BLK_ELEMS (BLK * KPAD)        // 4608
#define BLK_BYTES (BLK_ELEMS * 2)     // 9216
#define NKC       (H_ / BLK)          // 16 k-chunks
#define NBM       (B_ / BLK)          // 8
#define NBN       (H_ / BLK)          // 16
#define NS        6                   // pipeline stages
#define PAIR_BYTES (2 * BLK_BYTES)    // 18432 (hi+lo)
#define STG_BYTES  (2 * PAIR_BYTES)   // 36864 (A pair + W pair)
#define SMEM_STG0  128                // mbarrier region
#define STEP_SMEM  (SMEM_STG0 + NS * STG_BYTES)   // 221312 bytes

// ---------------- device scratch (no runtime allocation allowed) ----------------
__device__ float g_h[B_ * H_];
__device__ __align__(128) __nv_bfloat16 g_wt[(size_t)NBN * NKC * 2 * BLK_ELEMS];
__device__ __align__(128) __nv_bfloat16 g_at[2][(size_t)NBM * NKC * 2 * BLK_ELEMS];
__device__ float g_parto[4][B_ * C_];

// ---------------- base-ISA PTX helpers (compute_103-safe) ----------------
__device__ __forceinline__ uint32_t smem_u32(const void* p) {
    uint32_t a;
    asm("{ .reg .u64 t; cvta.to.shared.u64 t, %1; cvt.u32.u64 %0, t; }"
        : "=r"(a) : "l"(p));
    return a;
}
#define MBAR_INIT(a, c) \
    asm volatile("mbarrier.init.shared.b64 [%0], %1;" :: "r"(a), "r"(c) : "memory")
#define MBAR_ARRIVE(a) \
    asm volatile("mbarrier.arrive.shared.b64 _, [%0];" :: "r"(a) : "memory")
#define MBAR_EXPECT_TX(a, n) \
    asm volatile("mbarrier.arrive.expect_tx.shared.b64 _, [%0], %1;" \
                 :: "r"(a), "r"(n) : "memory")
#define MBAR_WAIT(a, ph) do {                                                     \
    uint32_t _m = (a), _p = (ph), _d;                                             \
    asm volatile("{\n\t.reg .pred p;\n\t"                                         \
        "mbarrier.try_wait.parity.acquire.cta.shared::cta.b64 p, [%1], %2;\n\t"   \
        "selp.b32 %0, 1, 0, p;\n\t}" : "=r"(_d) : "r"(_m), "r"(_p) : "memory");   \
    if (!_d) {                                                                     \
        asm volatile("{\n\t.reg .pred P1;\n\tWL_%=:\n\t"                          \
            "mbarrier.try_wait.parity.acquire.cta.shared::cta.b64 P1, [%0], %1, 0x989680;\n\t" \
            "@P1 bra.uni WD_%=;\n\tbra.uni WL_%=;\n\tWD_%=:\n\t}"                 \
            :: "r"(_m), "r"(_p) : "memory");                                      \
    } } while (0)
#define BULK_G2S(dst, src, n, mbar) \
    asm volatile("cp.async.bulk.shared::cluster.global.mbarrier::complete_tx::bytes " \
        "[%0], [%1], %2, [%3];" \
        :: "r"(dst), "l"(src), "r"(n), "r"(mbar) : "memory")

#define LDSM4(r, addr) \
    asm volatile("ldmatrix.sync.aligned.m8n8.x4.shared.b16 {%0,%1,%2,%3}, [%4];" \
        : "=r"((r)[0]), "=r"((r)[1]), "=r"((r)[2]), "=r"((r)[3]) : "r"(addr))

#define MMA16816(c, a, b0, b1) \
    asm volatile("mma.sync.aligned.m16n8k16.row.col.f32.bf16.bf16.f32 " \
        "{%0,%1,%2,%3}, {%4,%5,%6,%7}, {%8,%9}, {%0,%1,%2,%3};" \
        : "+f"((c)[0]), "+f"((c)[1]), "+f"((c)[2]), "+f"((c)[3]) \
        : "r"((a)[0]), "r"((a)[1]), "r"((a)[2]), "r"((a)[3]), "r"(b0), "r"(b1))

// =====================================================================
// per-step kernel: acc = Ahi*Whi^T + Ahi*Wlo^T + Alo*Whi^T (bf16 MMA),
// fused epilogue h = tanh(acc + x_t*W_hx + b_h) -> next-step tiled hi/lo.
// grid (16, 8) = 128 CTAs, 288 threads:
//   warps 0-7 compute (32x16 tiles, 2/SMSP), warp 8 dedicated producer.
// 6-stage mbarrier ring, cp.async.bulk loads, NO __syncthreads in loop.
// =====================================================================
__global__ void __launch_bounds__(288, 1)
rnn_step(const __nv_bfloat16* __restrict__ at_in,
         __nv_bfloat16* __restrict__ at_out,
         const __nv_bfloat16* __restrict__ wt,
         const float* __restrict__ x, const float* __restrict__ whx,
         const float* __restrict__ bh,
         float* __restrict__ hout,
         int t, int last)
{
    extern __shared__ char smem[];
    const uint32_t sb = smem_u32(smem);
    const int tid  = threadIdx.x;
    const int wid  = tid >> 5;
    const int lane = tid & 31;
    const int bn   = blockIdx.x;        // 0..15
    const int bm   = blockIdx.y;        // 0..7

    // mbarriers: full[s] at sb+8s, empty[s] at sb+64+8s
    if (tid == 0) {
#pragma unroll
        for (int s = 0; s < NS; s++) {
            MBAR_INIT(sb + 8 * s, 1);        // full: producer arrive+tx
            MBAR_INIT(sb + 64 + 8 * s, 8);   // empty: 1 arrive per compute warp
        }
    }
    __syncthreads();

    const __nv_bfloat16* srcA = at_in + (size_t)(bm * NKC) * 2 * BLK_ELEMS;
    const __nv_bfloat16* srcW = wt    + (size_t)(bn * NKC) * 2 * BLK_ELEMS;

    if (wid == 8) {
        // ================ dedicated producer warp ================
        if (lane == 0) {
#pragma unroll
            for (int c0 = 0; c0 < NS; c0++) {
                const uint32_t stg = sb + SMEM_STG0 + c0 * STG_BYTES;
                MBAR_EXPECT_TX(sb + 8 * c0, STG_BYTES);
                BULK_G2S(stg,              srcA + (size_t)c0 * 2 * BLK_ELEMS, PAIR_BYTES, sb + 8 * c0);
                BULK_G2S(stg + PAIR_BYTES, srcW + (size_t)c0 * 2 * BLK_ELEMS, PAIR_BYTES, sb + 8 * c0);
            }
            int s = 0, ph = 0;
#pragma unroll 1
            for (int c2 = NS; c2 < NKC; c2++) {
                MBAR_WAIT(sb + 64 + 8 * s, ph);      // stage s freed by all warps
                MBAR_EXPECT_TX(sb + 8 * s, STG_BYTES);
                const uint32_t stg = sb + SMEM_STG0 + s * STG_BYTES;
                BULK_G2S(stg,              srcA + (size_t)c2 * 2 * BLK_ELEMS, PAIR_BYTES, sb + 8 * s);
                BULK_G2S(stg + PAIR_BYTES, srcW + (size_t)c2 * 2 * BLK_ELEMS, PAIR_BYTES, sb + 8 * s);
                s++; if (s == NS) { s = 0; ph ^= 1; }
            }
        }
        return;
    }

    // ================ compute warps 0-7 ================
    const int wm = (wid & 1) * 32;      // 2 m-warps
    const int wn = (wid >> 1) * 16;     // 4 n-warps

    // -------- epilogue constants prefetch --------
    const int qc = (lane & 3) * 2;
    float ew0[2], ew1[2], eb0[2], eb1[2];
#pragma unroll
    for (int ni = 0; ni < 2; ni++) {
        const int j = bn * BLK + wn + ni * 8 + qc;
        ew0[ni] = whx[j];  ew1[ni] = whx[j + 1];
        eb0[ni] = bh[j];   eb1[ni] = bh[j + 1];
    }
    float exv[2][2];
#pragma unroll
    for (int mi = 0; mi < 2; mi++)
#pragma unroll
        for (int hf = 0; hf < 2; hf++) {
            const int gm = bm * BLK + wm + mi * 16 + (lane >> 2) + hf * 8;
            exv[mi][hf] = x[(size_t)gm * T_ + t];
        }

    float acc[2][2][4];                 // [mi][ni][quad]
#pragma unroll
    for (int mi = 0; mi < 2; mi++)
#pragma unroll
        for (int ni = 0; ni < 2; ni++)
#pragma unroll
            for (int q = 0; q < 4; q++) acc[mi][ni][q] = 0.0f;

    const int tdiv8 = lane >> 3;
    const int tmod8 = lane & 7;
    const int arow = wm + ((tdiv8 & 1) << 3) + tmod8;   // A ldmatrix row base
    const int wrow = wn + ((tdiv8 >> 1) << 3) + tmod8;  // W ldmatrix row
    const int acol = (tdiv8 >> 1) << 3;                 // A ldmatrix col base
    const int wcol = (tdiv8 & 1) << 3;                  // W ldmatrix col base

    // fragment double buffers across ks
    uint32_t Ah[2][2][4], Al[2][2][4], Wh[2][4], Wl[2][4];

    // ---------------- mainloop ----------------
    int s = 0, ph = 0;
#pragma unroll 1
    for (int c = 0; c < NKC; c++) {
        MBAR_WAIT(sb + 8 * s, ph);                  // full[s]
        const uint32_t base = sb + SMEM_STG0 + s * STG_BYTES;

        // prefetch ks=0 fragments into buffer 0
#pragma unroll
        for (int mi = 0; mi < 2; mi++) {
            const uint32_t off = base + (uint32_t)((arow + mi * 16) * KPAD + acol) * 2;
            LDSM4(Ah[0][mi], off);
            LDSM4(Al[0][mi], off + BLK_BYTES);
        }
        {
            const uint32_t off = base + PAIR_BYTES + (uint32_t)(wrow * KPAD + wcol) * 2;
            LDSM4(Wh[0], off);
            LDSM4(Wl[0], off + BLK_BYTES);
        }

#pragma unroll
        for (int ks = 0; ks < 4; ks++) {
            const int cur = ks & 1, nxt = cur ^ 1;
            if (ks < 3) {   // prefetch next k-slice before this slice's MMAs
                const int col = (ks + 1) * 16;
#pragma unroll
                for (int mi = 0; mi < 2; mi++) {
                    const uint32_t off = base + (uint32_t)((arow + mi * 16) * KPAD + col + acol) * 2;
                    LDSM4(Ah[nxt][mi], off);
                    LDSM4(Al[nxt][mi], off + BLK_BYTES);
                }
                const uint32_t off = base + PAIR_BYTES + (uint32_t)(wrow * KPAD + col + wcol) * 2;
                LDSM4(Wh[nxt], off);
                LDSM4(Wl[nxt], off + BLK_BYTES);
            }
            // products: Ahi*Whi, Ahi*Wlo, Alo*Whi
#pragma unroll
            for (int p = 0; p < 3; p++) {
                uint32_t (*A)[4] = (p == 2) ? Al[cur] : Ah[cur];
                uint32_t* W      = (p == 1) ? Wl[cur] : Wh[cur];
#pragma unroll
                for (int mi = 0; mi < 2; mi++)
#pragma unroll
                    for (int ni = 0; ni < 2; ni++)
                        MMA16816(acc[mi][ni], A[mi], W[ni * 2], W[ni * 2 + 1]);
            }
        }
        if (lane == 0) MBAR_ARRIVE(sb + 64 + 8 * s);    // empty[s], 1/warp
        s++; if (s == NS) { s = 0; ph ^= 1; }
    }

    // ---------------- fused epilogue -> tiled A blocks for next step ----------------
    __nv_bfloat16* aout_hi = at_out + ((size_t)(bm * NKC + bn) * 2) * BLK_ELEMS;
    __nv_bfloat16* aout_lo = aout_hi + BLK_ELEMS;
#pragma unroll
    for (int ni = 0; ni < 2; ni++) {
        const int jl = wn + ni * 8 + qc;          // 0..63 within block
        const int j  = bn * BLK + jl;
#pragma unroll
        for (int mi = 0; mi < 2; mi++) {
#pragma unroll
            for (int hf = 0; hf < 2; hf++) {
                const int m  = wm + mi * 16 + (lane >> 2) + hf * 8;
                const int gm = bm * BLK + m;
                const float xv = exv[mi][hf];
                const float c0 = acc[mi][ni][hf * 2];
                const float c1 = acc[mi][ni][hf * 2 + 1];
                const float h0 = tanhf(fmaf(xv, ew0[ni], eb0[ni]) + c0);
                const float h1 = tanhf(fmaf(xv, ew1[ni], eb1[ni]) + c1);
                const __nv_bfloat16 h0h = __float2bfloat16(h0);
                const __nv_bfloat16 h1h = __float2bfloat16(h1);
                const int idx = m * KPAD + jl;
                __nv_bfloat162 hi2; hi2.x = h0h; hi2.y = h1h;
                *reinterpret_cast<__nv_bfloat162*>(aout_hi + idx) = hi2;
                __nv_bfloat162 lo2;
                lo2.x = __float2bfloat16(h0 - __bfloat162float(h0h));
                lo2.y = __float2bfloat16(h1 - __bfloat162float(h1h));
                *reinterpret_cast<__nv_bfloat162*>(aout_lo + idx) = lo2;
                if (last) {
                    float2 f2; f2.x = h0; f2.y = h1;
                    *reinterpret_cast<float2*>(hout + (size_t)gm * H_ + j) = f2;
                }
            }
        }
    }
}

// ================= one-time helpers =================
__global__ void split_w(const float* __restrict__ w, __nv_bfloat16* __restrict__ wt)
{
    const int i = blockIdx.x * blockDim.x + threadIdx.x;   // 1M elements
    const int n = i >> 10, k = i & 1023;
    const float v = w[i];
    const __nv_bfloat16 h = __float2bfloat16(v);
    const __nv_bfloat16 l = __float2bfloat16(v - __bfloat162float(h));
    const size_t base = ((size_t)((n >> 6) * NKC + (k >> 6)) * 2) * BLK_ELEMS
                      + (n & 63) * KPAD + (k & 63);
    wt[base] = h;
    wt[base + BLK_ELEMS] = l;
}

__global__ void init_h(const float* __restrict__ x, const float* __restrict__ whx,
                       const float* __restrict__ bh, __nv_bfloat16* __restrict__ at0)
{
    const int idx = blockIdx.x * blockDim.x + threadIdx.x;  // 512*1024
    const int b = idx >> 10, j = idx & 1023;
    const float hs = tanhf(fmaf(x[(size_t)b * T_], whx[j], bh[j]));
    const __nv_bfloat16 hb = __float2bfloat16(hs);
    const size_t base = ((size_t)((b >> 6) * NKC + (j >> 6)) * 2) * BLK_ELEMS
                      + (b & 63) * KPAD + (j & 63);
    at0[base] = hb;
    at0[base + BLK_ELEMS] = __float2bfloat16(hs - __bfloat162float(hb));
}

// ================= head GEMM (proven SIMT split-K, N=128) =================
#define GBM   128
#define GBK   32
#define GBMp  132
#define GKS   4
#define GKPS  (H_ / GKS)
#define GNCH  (GKPS / GBK)

__device__ __forceinline__ void ffma2(unsigned long long& d,
                                      unsigned long long a, unsigned long long b) {
    asm("fma.rn.f32x2 %0, %1, %2, %0;" : "+l"(d) : "l"(a), "l"(b));
}
__device__ __forceinline__ unsigned long long dup2(float w) {
    unsigned long long r;
    asm("mov.b64 %0, {%1, %1};" : "=l"(r) : "f"(w));
    return r;
}

__global__ void __launch_bounds__(256, 1)
gemm_part_kernel(const float* __restrict__ A, const float* __restrict__ W,
                 float* __restrict__ part, int N)
{
    extern __shared__ float fsm[];
    float (*Hs)[GBK][GBMp] = reinterpret_cast<float (*)[GBK][GBMp]>(fsm);
    float (*Ws)[GBK][GBMp] = reinterpret_cast<float (*)[GBK][GBMp]>(fsm + 2 * GBK * GBMp);

    const int tid = threadIdx.x;
    const int bn = blockIdx.x, bm = blockIdx.y, ks = blockIdx.z;
    const int k0 = ks * GKPS;
    const int lr = tid >> 3, lk = (tid & 7) << 2;
    const float* Ag = A + (size_t)(bm * GBM + lr) * H_ + k0 + lk;
    const float* Wg = W + (size_t)(bn * 128 + lr) * H_ + k0 + lk;
    const int tm = (tid & 15) * 8, tn = (tid >> 4) * 8;

    unsigned long long acc[4][8];
#pragma unroll
    for (int i = 0; i < 4; i++)
#pragma unroll
        for (int j = 0; j < 8; j++) acc[i][j] = 0ull;

    float4 ra[4], rb[4];
    auto LDG = [&](int ch) {
        const float* a = Ag + ch * GBK;
        const float* w = Wg + ch * GBK;
#pragma unroll
        for (int p = 0; p < 4; p++) {
            ra[p] = *reinterpret_cast<const float4*>(a + (size_t)p * 32 * H_);
            rb[p] = *reinterpret_cast<const float4*>(w + (size_t)p * 32 * H_);
        }
    };
    auto STS = [&](int buf) {
#pragma unroll
        for (int p = 0; p < 4; p++) {
            const float* va = reinterpret_cast<const float*>(&ra[p]);
            const float* vb = reinterpret_cast<const float*>(&rb[p]);
            const int m = p * 32 + lr;
#pragma unroll
            for (int q = 0; q < 4; q++) {
                Hs[buf][lk + q][m] = va[q];
                Ws[buf][lk + q][m] = vb[q];
            }
        }
    };
    auto COMPUTE = [&](int buf) {
#pragma unroll 4
        for (int kk = 0; kk < GBK; kk++) {
            ulonglong2 hA = *reinterpret_cast<const ulonglong2*>(&Hs[buf][kk][tm]);
            ulonglong2 hB = *reinterpret_cast<const ulonglong2*>(&Hs[buf][kk][tm + 4]);
            float4 wa = *reinterpret_cast<const float4*>(&Ws[buf][kk][tn]);
            float4 wb = *reinterpret_cast<const float4*>(&Ws[buf][kk][tn + 4]);
            unsigned long long h[4] = { hA.x, hA.y, hB.x, hB.y };
            unsigned long long w[8] = { dup2(wa.x), dup2(wa.y), dup2(wa.z), dup2(wa.w),
                                        dup2(wb.x), dup2(wb.y), dup2(wb.z), dup2(wb.w) };
#pragma unroll
            for (int i = 0; i < 4; i++)
#pragma unroll
                for (int j = 0; j < 8; j++) ffma2(acc[i][j], h[i], w[j]);
        }
    };

    LDG(0); STS(0); LDG(1);
    __syncthreads();
#pragma unroll 1
    for (int ch = 0; ch < GNCH; ch++) {
        const int buf = ch & 1;
        if (ch + 1 < GNCH) STS(buf ^ 1);
        if (ch + 2 < GNCH) LDG(ch + 2);
        COMPUTE(buf);
        __syncthreads();
    }

    float* P = part + (size_t)ks * B_ * N + (size_t)(bm * GBM) * N + bn * 128;
#pragma unroll
    for (int i = 0; i < 4; i++) {
        const int r0 = tm + 2 * i;
        float2 f[8];
#pragma unroll
        for (int j = 0; j < 8; j++) f[j] = *reinterpret_cast<float2*>(&acc[i][j]);
        *reinterpret_cast<float4*>(P + (size_t)r0 * N + tn)           = make_float4(f[0].x, f[1].x, f[2].x, f[3].x);
        *reinterpret_cast<float4*>(P + (size_t)r0 * N + tn + 4)       = make_float4(f[4].x, f[5].x, f[6].x, f[7].x);
        *reinterpret_cast<float4*>(P + (size_t)(r0 + 1) * N + tn)     = make_float4(f[0].y, f[1].y, f[2].y, f[3].y);
        *reinterpret_cast<float4*>(P + (size_t)(r0 + 1) * N + tn + 4) = make_float4(f[4].y, f[5].y, f[6].y, f[7].y);
    }
}

__global__ void combine_o(const float* __restrict__ parto,
                          const float* __restrict__ bp, float* __restrict__ out)
{
    const int idx = blockIdx.x * blockDim.x + threadIdx.x;
    const int b = idx >> 5;
    const int c = (idx & 31) << 2;
    float4 s = *reinterpret_cast<const float4*>(bp + c);
    const size_t off = (size_t)b * C_ + c;
#pragma unroll
    for (int z = 0; z < GKS; z++) {
        float4 p = *reinterpret_cast<const float4*>(parto + (size_t)z * B_ * C_ + off);
        s.x += p.x; s.y += p.y; s.z += p.z; s.w += p.w;
    }
    *reinterpret_cast<float4*>(out + off) = s;
}

// ================= launch =================
extern "C" void kernel_launch(void* const* d_in, const int* in_sizes, int n_in,
                              void* d_out, int out_size)
{
    const float* x   = (const float*)d_in[0];   // [512,256]
    const float* whx = (const float*)d_in[1];   // [1024,1]
    const float* whh = (const float*)d_in[2];   // [1024,1024]
    const float* bh  = (const float*)d_in[3];   // [1024]
    const float* wph = (const float*)d_in[4];   // [128,1024]
    const float* bp  = (const float*)d_in[5];   // [128]
    float* out = (float*)d_out;                 // [512,128]

    float *h, *parto;
    __nv_bfloat16 *wt, *at;
    cudaGetSymbolAddress((void**)&h,     g_h);
    cudaGetSymbolAddress((void**)&wt,    g_wt);
    cudaGetSymbolAddress((void**)&at,    g_at);
    cudaGetSymbolAddress((void**)&parto, g_parto);
    const size_t ABUF = (size_t)NBM * NKC * 2 * BLK_ELEMS;

    cudaFuncSetAttribute(rnn_step, cudaFuncAttributeMaxDynamicSharedMemorySize, STEP_SMEM);
    const size_t gsmem = (size_t)2 * GBK * GBMp * sizeof(float) * 2;
    cudaFuncSetAttribute(gemm_part_kernel, cudaFuncAttributeMaxDynamicSharedMemorySize, (int)gsmem);

    // one-time: split W_hh into tiled hi/lo blocks
    split_w<<<4096, 256>>>(whh, wt);

    // step 0: h = tanh(x_0 * W_hx^T + b_h) -> tiled A buf 0
    init_h<<<2048, 256>>>(x, whx, bh, at);

    // steps 1..255 on tensor cores
    for (int t = 1; t < T_; t++) {
        const int ib = (t - 1) & 1, ob = t & 1;
        rnn_step<<<dim3(NBN, NBM), 288, STEP_SMEM>>>(
            at + (size_t)ib * ABUF, at + (size_t)ob * ABUF, wt,
            x, whx, bh, h, t, (t == T_ - 1) ? 1 : 0);
    }

    // head: out = h_last @ W_ph^T + b_p
    gemm_part_kernel<<<dim3(1, B_ / GBM, GKS), 256, gsmem>>>(h, wph, parto, C_);
    combine_o<<<(B_ * C_ / 4) / 256, 256>>>(parto, bp, out);
}